// round 1
// baseline (speedup 1.0000x reference)
#include <cuda_runtime.h>
#include <math.h>

#define NE 50000
#define NU 150000
#define NS 10000
#define HD 256
#define KD 768

// ---------------- scratch (static __device__, no allocations) ----------------
__device__ float g_A[(size_t)NE * KD];     // per row: [aggr_ue(256) | aggr_se(256) | he(256)]
__device__ float g_he[(size_t)NE * HD];    // he after conv+leaky+gated residual
__device__ float g_WeT[KD * HD];           // W_e transposed: [k][h]
__device__ float g_WcT[KD * HD];           // combined conv weight transposed: [k][h]
__device__ float g_bias2[HD];              // bl_ue + bl_se
__device__ float g_sum8[NE * 8];
__device__ float g_sum1[NE];
__device__ int   g_cnt_ue[NE];
__device__ int   g_cnt_se[NE];

// ---------------- zero accumulators (must re-zero every graph replay) --------
__global__ void zero_kernel() {
    int i = blockIdx.x * blockDim.x + threadIdx.x;
    int stride = gridDim.x * blockDim.x;
    for (int j = i; j < NE * 8; j += stride) g_sum8[j] = 0.f;
    for (int j = i; j < NE; j += stride) { g_sum1[j] = 0.f; g_cnt_ue[j] = 0; g_cnt_se[j] = 0; }
}

// ---------------- weight prep: transpose + combine -------------------------
__global__ void prep_kernel(const float* __restrict__ W_e,
                            const float* __restrict__ Wl_ue, const float* __restrict__ Wl_se,
                            const float* __restrict__ Wr_ue, const float* __restrict__ Wr_se,
                            const float* __restrict__ bl_ue, const float* __restrict__ bl_se) {
    int idx = blockIdx.x * 256 + threadIdx.x;   // 768 blocks x 256 = 768*256 exactly
    if (idx < HD) g_bias2[idx] = bl_ue[idx] + bl_se[idx];
    int k = idx >> 8;
    int h = idx & 255;
    g_WeT[idx] = W_e[h * KD + k];
    float w;
    if (k < 256)      w = Wl_ue[h * HD + k];
    else if (k < 512) w = Wl_se[h * HD + (k - 256)];
    else              w = Wr_ue[h * HD + (k - 512)] + Wr_se[h * HD + (k - 512)];
    g_WcT[idx] = w;
}

// ---------------- edge aggregation (raw 8-wide / 1-wide features) -----------
__global__ void agg_ue_kernel(const int* __restrict__ src, const int* __restrict__ dst,
                              const float* __restrict__ x_url, int nE) {
    int t = blockIdx.x * blockDim.x + threadIdx.x;
    int e = t >> 3, c = t & 7;
    if (e >= nE) return;
    int s = src[e], d = dst[e];
    atomicAdd(&g_sum8[d * 8 + c], x_url[s * 8 + c]);
    if (c == 0) atomicAdd(&g_cnt_ue[d], 1);
}

__global__ void agg_se_kernel(const int* __restrict__ src, const int* __restrict__ dst,
                              const float* __restrict__ x_sender, int nE) {
    int e = blockIdx.x * blockDim.x + threadIdx.x;
    if (e >= nE) return;
    int d = dst[e];
    atomicAdd(&g_sum1[d], x_sender[src[e]]);
    atomicAdd(&g_cnt_se[d], 1);
}

// ---------------- project aggregates into A[:,0:512] ------------------------
// aggr_hu = count>0 ? mean(x_url) @ W_u^T + b_u : 0   (linearity of projection)
// aggr_hs = count>0 ? mean(x_sender) * W_s + b_s : 0
__global__ void proj_aggr_kernel(const float* __restrict__ W_u, const float* __restrict__ b_u,
                                 const float* __restrict__ W_s, const float* __restrict__ b_s) {
    int n = blockIdx.x;
    int h = threadIdx.x;
    __shared__ float s8[8];
    __shared__ float s1v;
    __shared__ int scu, scs;
    if (h < 8) s8[h] = g_sum8[n * 8 + h];
    if (h == 8) s1v = g_sum1[n];
    if (h == 9) scu = g_cnt_ue[n];
    if (h == 10) scs = g_cnt_se[n];
    __syncthreads();
    int cu = scu, cs = scs;
    float out_u = 0.f;
    if (cu > 0) {
        float inv = 1.f / (float)cu;
        float acc = b_u[h];
#pragma unroll
        for (int c = 0; c < 8; c++) acc += (s8[c] * inv) * W_u[h * 8 + c];
        out_u = acc;
    }
    g_A[(size_t)n * KD + h] = out_u;
    float out_s = 0.f;
    if (cs > 0) out_s = (s1v / (float)cs) * W_s[h] + b_s[h];
    g_A[(size_t)n * KD + 256 + h] = out_s;
}

// ---------------- SGEMM: C[M,256] = A[M,768] * BT[768,256] + bias -----------
// MODE 0: A = x_email, BT = g_WeT, bias = ext; write he into g_A[:,512:768]
// MODE 1: A = g_A,     BT = g_WcT, bias = g_bias2; fused epilogue:
//         he = alpha*leaky(0.5*out) + (1-alpha)*resid, resid = g_A[:,512:768]
template <int MODE>
__global__ __launch_bounds__(256) void gemm_kernel(const float* __restrict__ A_ext,
                                                   const float* __restrict__ bias_ext,
                                                   const float* __restrict__ gate) {
    const float* A    = (MODE == 0) ? A_ext : g_A;
    const float* BT   = (MODE == 0) ? g_WeT : g_WcT;
    const float* bias = (MODE == 0) ? bias_ext : g_bias2;

    __shared__ float As[16][64];
    __shared__ float Bs[16][256];

    int m0 = blockIdx.x * 64;
    int tid = threadIdx.x;
    int tx = tid & 31, ty = tid >> 5;

    float acc[8][8];
#pragma unroll
    for (int i = 0; i < 8; i++)
#pragma unroll
        for (int j = 0; j < 8; j++) acc[i][j] = 0.f;

    int aRow = tid >> 2;
    int aK = (tid & 3) << 2;
    bool aValid = (m0 + aRow) < NE;
    const float* aPtr = A + (size_t)(m0 + aRow) * KD + aK;

    for (int k0 = 0; k0 < KD; k0 += 16) {
        float4 av = aValid ? *(const float4*)(aPtr + k0) : make_float4(0.f, 0.f, 0.f, 0.f);
        As[aK + 0][aRow] = av.x;
        As[aK + 1][aRow] = av.y;
        As[aK + 2][aRow] = av.z;
        As[aK + 3][aRow] = av.w;
#pragma unroll
        for (int it = 0; it < 4; it++) {
            int f = tid + it * 256;
            int kk = f >> 6;
            int n4 = (f & 63) << 2;
            *(float4*)&Bs[kk][n4] = *(const float4*)(BT + (size_t)(k0 + kk) * 256 + n4);
        }
        __syncthreads();
#pragma unroll
        for (int k = 0; k < 16; k++) {
            float a[8], b[8];
            *(float4*)&a[0] = *(float4*)&As[k][ty * 8];
            *(float4*)&a[4] = *(float4*)&As[k][ty * 8 + 4];
            *(float4*)&b[0] = *(float4*)&Bs[k][tx * 8];
            *(float4*)&b[4] = *(float4*)&Bs[k][tx * 8 + 4];
#pragma unroll
            for (int i = 0; i < 8; i++)
#pragma unroll
                for (int j = 0; j < 8; j++) acc[i][j] += a[i] * b[j];
        }
        __syncthreads();
    }

    float alpha = 0.f;
    if (MODE == 1) alpha = 1.f / (1.f + expf(-gate[0]));

#pragma unroll
    for (int i = 0; i < 8; i++) {
        int row = m0 + ty * 8 + i;
        if (row >= NE) continue;
#pragma unroll
        for (int j4 = 0; j4 < 2; j4++) {
            int col = tx * 8 + j4 * 4;
            float4 v;
            v.x = acc[i][j4 * 4 + 0] + bias[col + 0];
            v.y = acc[i][j4 * 4 + 1] + bias[col + 1];
            v.z = acc[i][j4 * 4 + 2] + bias[col + 2];
            v.w = acc[i][j4 * 4 + 3] + bias[col + 3];
            if (MODE == 0) {
                *(float4*)&g_A[(size_t)row * KD + 512 + col] = v;
            } else {
                float4 r = *(const float4*)&g_A[(size_t)row * KD + 512 + col];
                float t;
                t = 0.5f * v.x; t = t > 0.f ? t : 0.2f * t; v.x = alpha * t + (1.f - alpha) * r.x;
                t = 0.5f * v.y; t = t > 0.f ? t : 0.2f * t; v.y = alpha * t + (1.f - alpha) * r.y;
                t = 0.5f * v.z; t = t > 0.f ? t : 0.2f * t; v.z = alpha * t + (1.f - alpha) * r.z;
                t = 0.5f * v.w; t = t > 0.f ? t : 0.2f * t; v.w = alpha * t + (1.f - alpha) * r.w;
                *(float4*)&g_he[(size_t)row * HD + col] = v;
            }
        }
    }
}

// ---------------- KAN classifier: SiLU base + order-3 B-spline path ---------
__global__ __launch_bounds__(256) void kan_kernel(const float* __restrict__ base_w,
                                                  const float* __restrict__ spline_w,
                                                  float* __restrict__ out) {
    __shared__ float sbw[2 * 256];          // [o][h]
    __shared__ float ssw[8 * 2 * 256];      // [g][o][h]  (conflict-free on h)
    int tid = threadIdx.x;
    for (int i = tid; i < 512; i += 256) sbw[i] = base_w[i];
    for (int i = tid; i < 4096; i += 256) {
        int o = i >> 11;
        int h = (i >> 3) & 255;
        int g = i & 7;
        ssw[g * 512 + o * 256 + h] = spline_w[i];
    }
    __syncthreads();

    int warp = tid >> 5, lane = tid & 31;
    int base = blockIdx.x * 64;
    for (int nn = warp; nn < 64; nn += 8) {
        int n = base + nn;
        if (n >= NE) break;
        float acc0 = 0.f, acc1 = 0.f;
#pragma unroll
        for (int it = 0; it < 8; it++) {
            int h = it * 32 + lane;
            float x = g_he[(size_t)n * HD + h];
            float sil = x / (1.f + expf(-x));
            acc0 += sil * sbw[h];
            acc1 += sil * sbw[256 + h];
            // Cox-de Boor, uniform grid [-2.2 : 0.4 : 2.2], order 3
            float b[11];
#pragma unroll
            for (int i = 0; i < 11; i++) {
                float g0 = -2.2f + 0.4f * (float)i;
                float g1 = g0 + 0.4f;
                b[i] = (x >= g0 && x < g1) ? 1.f : 0.f;
            }
#pragma unroll
            for (int p = 1; p <= 3; p++) {
                float inv = 1.f / (0.4f * (float)p);
#pragma unroll
                for (int i = 0; i < 11 - p; i++) {
                    float gi = -2.2f + 0.4f * (float)i;
                    float left = (x - gi) * inv;
                    float right = ((gi + 0.4f * (float)(p + 1)) - x) * inv;
                    b[i] = left * b[i] + right * b[i + 1];
                }
            }
#pragma unroll
            for (int g = 0; g < 8; g++) {
                acc0 += b[g] * ssw[g * 512 + h];
                acc1 += b[g] * ssw[g * 512 + 256 + h];
            }
        }
#pragma unroll
        for (int off = 16; off; off >>= 1) {
            acc0 += __shfl_xor_sync(0xffffffff, acc0, off);
            acc1 += __shfl_xor_sync(0xffffffff, acc1, off);
        }
        if (lane == 0) {
            out[n * 2 + 0] = acc0;
            out[n * 2 + 1] = acc1;
        }
    }
}

// ---------------- launch ----------------------------------------------------
extern "C" void kernel_launch(void* const* d_in, const int* in_sizes, int n_in,
                              void* d_out, int out_size) {
    const float* x_email   = (const float*)d_in[0];
    const float* x_url     = (const float*)d_in[1];
    const float* x_sender  = (const float*)d_in[2];
    const float* W_e       = (const float*)d_in[3];
    const float* b_e       = (const float*)d_in[4];
    const float* W_u       = (const float*)d_in[5];
    const float* b_u       = (const float*)d_in[6];
    const float* W_s       = (const float*)d_in[7];
    const float* b_s       = (const float*)d_in[8];
    // d_in[9..11] = Wl_eu/bl_eu/Wr_eu (dead), d_in[18..20] = Wl_es/bl_es/Wr_es (dead)
    const float* Wl_ue     = (const float*)d_in[12];
    const float* bl_ue     = (const float*)d_in[13];
    const float* Wr_ue     = (const float*)d_in[14];
    const float* Wl_se     = (const float*)d_in[15];
    const float* bl_se     = (const float*)d_in[16];
    const float* Wr_se     = (const float*)d_in[17];
    const float* gate      = (const float*)d_in[21];
    const float* kan_base  = (const float*)d_in[22];
    const float* kan_spline= (const float*)d_in[23];
    const int*   ue_src    = (const int*)d_in[26];
    const int*   ue_dst    = (const int*)d_in[27];
    const int*   se_src    = (const int*)d_in[28];
    const int*   se_dst    = (const int*)d_in[29];
    int n_ue = in_sizes[26];
    int n_se = in_sizes[28];
    float* out = (float*)d_out;

    zero_kernel<<<512, 256>>>();
    prep_kernel<<<KD, 256>>>(W_e, Wl_ue, Wl_se, Wr_ue, Wr_se, bl_ue, bl_se);
    agg_ue_kernel<<<(n_ue * 8 + 255) / 256, 256>>>(ue_src, ue_dst, x_url, n_ue);
    agg_se_kernel<<<(n_se + 255) / 256, 256>>>(se_src, se_dst, x_sender, n_se);
    gemm_kernel<0><<<(NE + 63) / 64, 256>>>(x_email, b_e, nullptr);
    proj_aggr_kernel<<<NE, 256>>>(W_u, b_u, W_s, b_s);
    gemm_kernel<1><<<(NE + 63) / 64, 256>>>(nullptr, nullptr, gate);
    kan_kernel<<<(NE + 63) / 64, 256>>>(kan_base, kan_spline, out);
}

// round 4
// speedup vs baseline: 1.9180x; 1.9180x over previous
#include <cuda_runtime.h>
#include <cuda_bf16.h>
#include <stdint.h>
#include <math.h>

#define NE 50000
#define NU 150000
#define NS 10000
#define HD 256
#define KD 768

// ---------------- scratch (static __device__, no allocations) ----------------
__device__ float g_A[(size_t)NE * KD];     // per row: [aggr_ue(256) | aggr_se(256) | he_pre(256)]
__device__ float g_he[(size_t)NE * HD];    // he after conv+leaky+gated residual
__device__ __nv_bfloat16 g_WeH[HD * KD];   // W_e split-hi, [N=256][K=768]
__device__ __nv_bfloat16 g_WeL[HD * KD];   // W_e split-lo
__device__ __nv_bfloat16 g_WcH[HD * KD];   // combined conv weight split-hi, [N][K]
__device__ __nv_bfloat16 g_WcL[HD * KD];
__device__ float g_bias2[HD];              // bl_ue + bl_se
__device__ float g_sum8[NE * 8];
__device__ float g_sum1[NE];
__device__ int   g_cnt_ue[NE];
__device__ int   g_cnt_se[NE];

// ---------------- zero accumulators (re-zeroed every graph replay) ----------
__global__ void zero_kernel() {
    int i = blockIdx.x * blockDim.x + threadIdx.x;
    int stride = gridDim.x * blockDim.x;
    for (int j = i; j < NE * 8; j += stride) g_sum8[j] = 0.f;
    for (int j = i; j < NE; j += stride) { g_sum1[j] = 0.f; g_cnt_ue[j] = 0; g_cnt_se[j] = 0; }
}

// ---------------- weight prep: split fp32 -> bf16 hi/lo ---------------------
__global__ void prep_kernel(const float* __restrict__ W_e,
                            const float* __restrict__ Wl_ue, const float* __restrict__ Wl_se,
                            const float* __restrict__ Wr_ue, const float* __restrict__ Wr_se,
                            const float* __restrict__ bl_ue, const float* __restrict__ bl_se) {
    int idx = blockIdx.x * 256 + threadIdx.x;    // 768 blocks * 256 = 196608 = 256*768
    if (idx < HD) g_bias2[idx] = bl_ue[idx] + bl_se[idx];
    int n = idx / KD;
    int k = idx % KD;
    float we = W_e[idx];
    __nv_bfloat16 h = __float2bfloat16(we);
    g_WeH[idx] = h;
    g_WeL[idx] = __float2bfloat16(we - __bfloat162float(h));
    float w;
    if (k < 256)      w = Wl_ue[n * HD + k];
    else if (k < 512) w = Wl_se[n * HD + (k - 256)];
    else              w = Wr_ue[n * HD + (k - 512)] + Wr_se[n * HD + (k - 512)];
    h = __float2bfloat16(w);
    g_WcH[idx] = h;
    g_WcL[idx] = __float2bfloat16(w - __bfloat162float(h));
}

// ---------------- edge aggregation (raw 8-wide / 1-wide features) -----------
__global__ void agg_ue_kernel(const int* __restrict__ src, const int* __restrict__ dst,
                              const float* __restrict__ x_url, int nE) {
    int t = blockIdx.x * blockDim.x + threadIdx.x;
    int e = t >> 3, c = t & 7;
    if (e >= nE) return;
    int s = src[e], d = dst[e];
    atomicAdd(&g_sum8[d * 8 + c], x_url[s * 8 + c]);
    if (c == 0) atomicAdd(&g_cnt_ue[d], 1);
}

__global__ void agg_se_kernel(const int* __restrict__ src, const int* __restrict__ dst,
                              const float* __restrict__ x_sender, int nE) {
    int e = blockIdx.x * blockDim.x + threadIdx.x;
    if (e >= nE) return;
    int d = dst[e];
    atomicAdd(&g_sum1[d], x_sender[src[e]]);
    atomicAdd(&g_cnt_se[d], 1);
}

// ---------------- project aggregates into A[:,0:512] ------------------------
__global__ void proj_aggr_kernel(const float* __restrict__ W_u, const float* __restrict__ b_u,
                                 const float* __restrict__ W_s, const float* __restrict__ b_s) {
    int n = blockIdx.x;
    int h = threadIdx.x;
    __shared__ float s8[8];
    __shared__ float s1v;
    __shared__ int scu, scs;
    if (h < 8) s8[h] = g_sum8[n * 8 + h];
    if (h == 8) s1v = g_sum1[n];
    if (h == 9) scu = g_cnt_ue[n];
    if (h == 10) scs = g_cnt_se[n];
    __syncthreads();
    int cu = scu, cs = scs;
    float out_u = 0.f;
    if (cu > 0) {
        float inv = 1.f / (float)cu;
        float acc = b_u[h];
#pragma unroll
        for (int c = 0; c < 8; c++) acc += (s8[c] * inv) * W_u[h * 8 + c];
        out_u = acc;
    }
    g_A[(size_t)n * KD + h] = out_u;
    float out_s = 0.f;
    if (cs > 0) out_s = (s1v / (float)cs) * W_s[h] + b_s[h];
    g_A[(size_t)n * KD + 256 + h] = out_s;
}

// ---------------- tensor-core split-bf16 GEMM -------------------------------
// C[M,256] = A[M,768] * W^T + bias, W stored [N=256][K=768] as bf16 hi/lo.
// Block tile 128x128 (grid.y selects n-half), 8 warps (2x4), warp tile 64x32.
// MODE 0: A = x_email, W = g_We*, bias = ext; write into g_A[:,512:768]
// MODE 1: A = g_A,     W = g_Wc*, bias = g_bias2; fused epilogue to g_he
#define KSTRIDE 40   // 32 halves + 8 pad per SMEM row

__device__ __forceinline__ void ldsm4(uint32_t addr, uint32_t& r0, uint32_t& r1,
                                      uint32_t& r2, uint32_t& r3) {
    asm volatile("ldmatrix.sync.aligned.m8n8.x4.shared.b16 {%0,%1,%2,%3}, [%4];"
                 : "=r"(r0), "=r"(r1), "=r"(r2), "=r"(r3) : "r"(addr));
}

__device__ __forceinline__ void mma16816(float* c, const uint32_t* a, uint32_t b0, uint32_t b1) {
    asm volatile("mma.sync.aligned.m16n8k16.row.col.f32.bf16.bf16.f32 "
                 "{%0,%1,%2,%3}, {%4,%5,%6,%7}, {%8,%9}, {%0,%1,%2,%3};"
                 : "+f"(c[0]), "+f"(c[1]), "+f"(c[2]), "+f"(c[3])
                 : "r"(a[0]), "r"(a[1]), "r"(a[2]), "r"(a[3]), "r"(b0), "r"(b1));
}

template <int MODE>
__global__ __launch_bounds__(256) void gemm_tc_kernel(const float* __restrict__ A_ext,
                                                      const float* __restrict__ bias_ext,
                                                      const float* __restrict__ gate) {
    const float* A = (MODE == 0) ? A_ext : g_A;
    const __nv_bfloat16* WH = (MODE == 0) ? g_WeH : g_WcH;
    const __nv_bfloat16* WL = (MODE == 0) ? g_WeL : g_WcL;
    const float* bias = (MODE == 0) ? bias_ext : g_bias2;

    __shared__ __nv_bfloat16 Ah[128 * KSTRIDE];
    __shared__ __nv_bfloat16 Al[128 * KSTRIDE];
    __shared__ __nv_bfloat16 Bh[128 * KSTRIDE];
    __shared__ __nv_bfloat16 Bl[128 * KSTRIDE];

    const int tid = threadIdx.x;
    const int lane = tid & 31;
    const int warp = tid >> 5;
    const int wm = warp & 1;        // 0..1  (64-row slabs)
    const int wn = warp >> 1;       // 0..3  (32-col slabs)
    const int m0 = blockIdx.x * 128;
    const int n0 = blockIdx.y * 128;

    float C[4][4][4];
#pragma unroll
    for (int i = 0; i < 4; i++)
#pragma unroll
        for (int j = 0; j < 4; j++)
#pragma unroll
            for (int q = 0; q < 4; q++) C[i][j][q] = 0.f;

    // ldmatrix lane addressing (within a 16x16 bf16 tile)
    const int a_row_off = ((lane >> 3) & 1) * 8 + (lane & 7);
    const int a_k_off   = ((lane >> 4) & 1) * 8;
    const int b_row_off = ((lane >> 4) & 1) * 8 + (lane & 7);
    const int b_k_off   = ((lane >> 3) & 1) * 8;

    const uint32_t sAh = (uint32_t)__cvta_generic_to_shared(Ah);
    const uint32_t sAl = (uint32_t)__cvta_generic_to_shared(Al);
    const uint32_t sBh = (uint32_t)__cvta_generic_to_shared(Bh);
    const uint32_t sBl = (uint32_t)__cvta_generic_to_shared(Bl);

    for (int k0 = 0; k0 < KD; k0 += 32) {
        // ---- stage A: 128 rows x 32 fp32 -> hi/lo bf16 SMEM ----
#pragma unroll
        for (int i = 0; i < 4; i++) {
            int f = tid + i * 256;          // 0..1023
            int row = f >> 3;               // 0..127
            int c4 = (f & 7) << 2;          // 0,4,..,28
            int gr = m0 + row;
            float4 v = (gr < NE) ? *(const float4*)(A + (size_t)gr * KD + k0 + c4)
                                 : make_float4(0.f, 0.f, 0.f, 0.f);
            __nv_bfloat16 h0 = __float2bfloat16(v.x);
            __nv_bfloat16 h1 = __float2bfloat16(v.y);
            __nv_bfloat16 h2 = __float2bfloat16(v.z);
            __nv_bfloat16 h3 = __float2bfloat16(v.w);
            __nv_bfloat16 l0 = __float2bfloat16(v.x - __bfloat162float(h0));
            __nv_bfloat16 l1 = __float2bfloat16(v.y - __bfloat162float(h1));
            __nv_bfloat16 l2 = __float2bfloat16(v.z - __bfloat162float(h2));
            __nv_bfloat16 l3 = __float2bfloat16(v.w - __bfloat162float(h3));
            int so = row * KSTRIDE + c4;
            Ah[so + 0] = h0; Ah[so + 1] = h1; Ah[so + 2] = h2; Ah[so + 3] = h3;
            Al[so + 0] = l0; Al[so + 1] = l1; Al[so + 2] = l2; Al[so + 3] = l3;
        }
        // ---- stage B: 128 rows(n) x 32 bf16 hi + lo ----
#pragma unroll
        for (int i = 0; i < 2; i++) {
            int f = tid + i * 256;          // 0..511
            int row = f >> 2;               // 0..127
            int c8 = (f & 3) << 3;          // 0,8,16,24 halves
            size_t go = (size_t)(n0 + row) * KD + k0 + c8;
            *(uint4*)&Bh[row * KSTRIDE + c8] = *(const uint4*)(WH + go);
            *(uint4*)&Bl[row * KSTRIDE + c8] = *(const uint4*)(WL + go);
        }
        __syncthreads();

#pragma unroll
        for (int kt = 0; kt < 2; kt++) {
            uint32_t Af_h[4][4];
            uint32_t Af_l[4][4];
#pragma unroll
            for (int mf = 0; mf < 4; mf++) {
                int row = wm * 64 + mf * 16 + a_row_off;
                uint32_t off = (uint32_t)(row * KSTRIDE + kt * 16 + a_k_off) * 2;
                ldsm4(sAh + off, Af_h[mf][0], Af_h[mf][1], Af_h[mf][2], Af_h[mf][3]);
                ldsm4(sAl + off, Af_l[mf][0], Af_l[mf][1], Af_l[mf][2], Af_l[mf][3]);
            }
            uint32_t Bf_h[2][4];
            uint32_t Bf_l[2][4];
#pragma unroll
            for (int nf = 0; nf < 2; nf++) {
                int row = wn * 32 + nf * 16 + b_row_off;
                uint32_t off = (uint32_t)(row * KSTRIDE + kt * 16 + b_k_off) * 2;
                ldsm4(sBh + off, Bf_h[nf][0], Bf_h[nf][1], Bf_h[nf][2], Bf_h[nf][3]);
                ldsm4(sBl + off, Bf_l[nf][0], Bf_l[nf][1], Bf_l[nf][2], Bf_l[nf][3]);
            }
#pragma unroll
            for (int mf = 0; mf < 4; mf++) {
#pragma unroll
                for (int j = 0; j < 4; j++) {
                    int nf = j >> 1;
                    int hh = j & 1;
                    uint32_t bh0 = Bf_h[nf][hh * 2];
                    uint32_t bh1 = Bf_h[nf][hh * 2 + 1];
                    uint32_t bl0 = Bf_l[nf][hh * 2];
                    uint32_t bl1 = Bf_l[nf][hh * 2 + 1];
                    mma16816(C[mf][j], Af_h[mf], bh0, bh1);
                    mma16816(C[mf][j], Af_h[mf], bl0, bl1);
                    mma16816(C[mf][j], Af_l[mf], bh0, bh1);
                }
            }
        }
        __syncthreads();
    }

    // ---- epilogue ----
    float alpha = 0.f;
    if (MODE == 1) alpha = 1.f / (1.f + expf(-gate[0]));
    const int g = lane >> 2, t = lane & 3;

#pragma unroll
    for (int mf = 0; mf < 4; mf++) {
        int r0 = m0 + wm * 64 + mf * 16 + g;
#pragma unroll
        for (int j = 0; j < 4; j++) {
            int col = n0 + wn * 32 + j * 8 + t * 2;
            float b0 = bias[col], b1 = bias[col + 1];
#pragma unroll
            for (int half = 0; half < 2; half++) {
                int row = r0 + half * 8;
                if (row >= NE) continue;
                float v0 = C[mf][j][half * 2 + 0] + b0;
                float v1 = C[mf][j][half * 2 + 1] + b1;
                if (MODE == 0) {
                    *(float2*)&g_A[(size_t)row * KD + 512 + col] = make_float2(v0, v1);
                } else {
                    float2 r = *(const float2*)&g_A[(size_t)row * KD + 512 + col];
                    float u;
                    u = 0.5f * v0; u = u > 0.f ? u : 0.2f * u; v0 = alpha * u + (1.f - alpha) * r.x;
                    u = 0.5f * v1; u = u > 0.f ? u : 0.2f * u; v1 = alpha * u + (1.f - alpha) * r.y;
                    *(float2*)&g_he[(size_t)row * HD + col] = make_float2(v0, v1);
                }
            }
        }
    }
}

// ---------------- KAN classifier: SiLU base + order-3 B-spline path ---------
__global__ __launch_bounds__(256) void kan_kernel(const float* __restrict__ base_w,
                                                  const float* __restrict__ spline_w,
                                                  float* __restrict__ out) {
    __shared__ float sbw[2 * 256];          // [o][h]
    __shared__ float ssw[8 * 2 * 256];      // [g][o][h]
    int tid = threadIdx.x;
    for (int i = tid; i < 512; i += 256) sbw[i] = base_w[i];
    for (int i = tid; i < 4096; i += 256) {
        int o = i >> 11;
        int h = (i >> 3) & 255;
        int g = i & 7;
        ssw[g * 512 + o * 256 + h] = spline_w[i];
    }
    __syncthreads();

    int warp = tid >> 5, lane = tid & 31;
    int base = blockIdx.x * 64;
    for (int nn = warp; nn < 64; nn += 8) {
        int n = base + nn;
        if (n >= NE) break;
        float acc0 = 0.f, acc1 = 0.f;
#pragma unroll
        for (int it = 0; it < 8; it++) {
            int h = it * 32 + lane;
            float x = g_he[(size_t)n * HD + h];
            float sil = x / (1.f + expf(-x));
            acc0 += sil * sbw[h];
            acc1 += sil * sbw[256 + h];
            float b[11];
#pragma unroll
            for (int i = 0; i < 11; i++) {
                float g0 = -2.2f + 0.4f * (float)i;
                float g1 = g0 + 0.4f;
                b[i] = (x >= g0 && x < g1) ? 1.f : 0.f;
            }
#pragma unroll
            for (int p = 1; p <= 3; p++) {
                float inv = 1.f / (0.4f * (float)p);
#pragma unroll
                for (int i = 0; i < 11 - p; i++) {
                    float gi = -2.2f + 0.4f * (float)i;
                    float left = (x - gi) * inv;
                    float right = ((gi + 0.4f * (float)(p + 1)) - x) * inv;
                    b[i] = left * b[i] + right * b[i + 1];
                }
            }
#pragma unroll
            for (int g = 0; g < 8; g++) {
                acc0 += b[g] * ssw[g * 512 + h];
                acc1 += b[g] * ssw[g * 512 + 256 + h];
            }
        }
#pragma unroll
        for (int off = 16; off; off >>= 1) {
            acc0 += __shfl_xor_sync(0xffffffff, acc0, off);
            acc1 += __shfl_xor_sync(0xffffffff, acc1, off);
        }
        if (lane == 0) {
            out[n * 2 + 0] = acc0;
            out[n * 2 + 1] = acc1;
        }
    }
}

// ---------------- launch ----------------------------------------------------
extern "C" void kernel_launch(void* const* d_in, const int* in_sizes, int n_in,
                              void* d_out, int out_size) {
    const float* x_email   = (const float*)d_in[0];
    const float* x_url     = (const float*)d_in[1];
    const float* x_sender  = (const float*)d_in[2];
    const float* W_e       = (const float*)d_in[3];
    const float* b_e       = (const float*)d_in[4];
    const float* W_u       = (const float*)d_in[5];
    const float* b_u       = (const float*)d_in[6];
    const float* W_s       = (const float*)d_in[7];
    const float* b_s       = (const float*)d_in[8];
    const float* Wl_ue     = (const float*)d_in[12];
    const float* bl_ue     = (const float*)d_in[13];
    const float* Wr_ue     = (const float*)d_in[14];
    const float* Wl_se     = (const float*)d_in[15];
    const float* bl_se     = (const float*)d_in[16];
    const float* Wr_se     = (const float*)d_in[17];
    const float* gate      = (const float*)d_in[21];
    const float* kan_base  = (const float*)d_in[22];
    const float* kan_spline= (const float*)d_in[23];
    const int*   ue_src    = (const int*)d_in[26];
    const int*   ue_dst    = (const int*)d_in[27];
    const int*   se_src    = (const int*)d_in[28];
    const int*   se_dst    = (const int*)d_in[29];
    int n_ue = in_sizes[26];
    int n_se = in_sizes[28];
    float* out = (float*)d_out;

    dim3 ggrid((NE + 127) / 128, 2);

    zero_kernel<<<512, 256>>>();
    prep_kernel<<<KD, 256>>>(W_e, Wl_ue, Wl_se, Wr_ue, Wr_se, bl_ue, bl_se);
    agg_ue_kernel<<<(n_ue * 8 + 255) / 256, 256>>>(ue_src, ue_dst, x_url, n_ue);
    agg_se_kernel<<<(n_se + 255) / 256, 256>>>(se_src, se_dst, x_sender, n_se);
    gemm_tc_kernel<0><<<ggrid, 256>>>(x_email, b_e, nullptr);
    proj_aggr_kernel<<<NE, 256>>>(W_u, b_u, W_s, b_s);
    gemm_tc_kernel<1><<<ggrid, 256>>>(nullptr, nullptr, gate);
    kan_kernel<<<(NE + 63) / 64, 256>>>(kan_base, kan_spline, out);
}

// round 5
// speedup vs baseline: 2.4751x; 1.2905x over previous
#include <cuda_runtime.h>
#include <cuda_bf16.h>
#include <stdint.h>
#include <math.h>

#define NE 50000
#define HD 256
#define KD 768
#define KB1 288   // gemm1 K: 256 he + 32 q (11 real + pad)

// ---------------- scratch (static __device__, no allocations) ----------------
__device__ __nv_bfloat16 g_AH[(size_t)NE * KB1];  // A' hi plane [NE][288]
__device__ __nv_bfloat16 g_AL[(size_t)NE * KB1];  // A' lo plane
__device__ float g_he[(size_t)NE * HD];           // final he (fp32, feeds KAN)
__device__ __nv_bfloat16 g_WeH[HD * KD];          // W_e hi [n][k] k<768
__device__ __nv_bfloat16 g_WeL[HD * KD];
__device__ __nv_bfloat16 g_WcH[HD * KB1];         // W' hi [n][k] k<288
__device__ __nv_bfloat16 g_WcL[HD * KB1];
__device__ float g_bias2[HD];                     // bl_ue + bl_se
__device__ float g_sum8[NE * 8];
__device__ float g_sum1[NE];
__device__ int   g_cnt_ue[NE];
__device__ int   g_cnt_se[NE];

// ---------------- zero accumulators (re-zeroed every graph replay) ----------
__global__ void zero_kernel() {
    int i = blockIdx.x * blockDim.x + threadIdx.x;
    int stride = gridDim.x * blockDim.x;
    for (int j = i; j < NE * 8; j += stride) g_sum8[j] = 0.f;
    for (int j = i; j < NE; j += stride) { g_sum1[j] = 0.f; g_cnt_ue[j] = 0; g_cnt_se[j] = 0; }
}

// ---------------- weight prep: split fp32 -> bf16 hi/lo ---------------------
__global__ void prep_kernel(const float* __restrict__ W_e,
                            const float* __restrict__ Wr_ue, const float* __restrict__ Wr_se,
                            const float* __restrict__ bl_ue, const float* __restrict__ bl_se) {
    int idx = blockIdx.x * 256 + threadIdx.x;   // 768 blocks: covers 256*768
    if (idx < HD) g_bias2[idx] = bl_ue[idx] + bl_se[idx];
    // W_e split: [n][k] identical layout to input
    float we = W_e[idx];
    __nv_bfloat16 h = __float2bfloat16(we);
    g_WeH[idx] = h;
    g_WeL[idx] = __float2bfloat16(we - __bfloat162float(h));
    // Wc rows k<256: combined Wr
    if (idx < HD * HD) {
        int n = idx >> 8, k = idx & 255;
        float w = Wr_ue[idx] + Wr_se[idx];
        __nv_bfloat16 wh = __float2bfloat16(w);
        g_WcH[n * KB1 + k] = wh;
        g_WcL[n * KB1 + k] = __float2bfloat16(w - __bfloat162float(wh));
    }
}

// ---------------- prep2: rank-11 correction columns of W' -------------------
// k=256+c: c<8: M_u[n][c]=sum_h Wl_ue[n,h]*W_u[h,c]; c=8: v_u; c=9: M_s; c=10: v_s; else 0
__global__ void prep2_kernel(const float* __restrict__ Wl_ue, const float* __restrict__ W_u,
                             const float* __restrict__ b_u,
                             const float* __restrict__ Wl_se, const float* __restrict__ W_s,
                             const float* __restrict__ b_s) {
    int n = blockIdx.x;
    int c = threadIdx.x;    // 0..31
    float acc = 0.f;
    if (c < 8) {
        for (int h = 0; h < HD; h++) acc += Wl_ue[n * HD + h] * W_u[h * 8 + c];
    } else if (c == 8) {
        for (int h = 0; h < HD; h++) acc += Wl_ue[n * HD + h] * b_u[h];
    } else if (c == 9) {
        for (int h = 0; h < HD; h++) acc += Wl_se[n * HD + h] * W_s[h];
    } else if (c == 10) {
        for (int h = 0; h < HD; h++) acc += Wl_se[n * HD + h] * b_s[h];
    }
    __nv_bfloat16 h = __float2bfloat16(acc);
    g_WcH[n * KB1 + 256 + c] = h;
    g_WcL[n * KB1 + 256 + c] = __float2bfloat16(acc - __bfloat162float(h));
}

// ---------------- edge aggregation ------------------------------------------
__global__ void agg_ue_kernel(const int* __restrict__ src, const int* __restrict__ dst,
                              const float* __restrict__ x_url, int nE) {
    int e = blockIdx.x * blockDim.x + threadIdx.x;
    if (e >= nE) return;
    int s = src[e], d = dst[e];
    const float4* xu = (const float4*)(x_url + (size_t)s * 8);
    float4 a = xu[0], b = xu[1];
    float* p = g_sum8 + (size_t)d * 8;
    asm volatile("red.global.add.v4.f32 [%0], {%1,%2,%3,%4};"
                 :: "l"(p), "f"(a.x), "f"(a.y), "f"(a.z), "f"(a.w) : "memory");
    asm volatile("red.global.add.v4.f32 [%0], {%1,%2,%3,%4};"
                 :: "l"(p + 4), "f"(b.x), "f"(b.y), "f"(b.z), "f"(b.w) : "memory");
    asm volatile("red.global.add.s32 [%0], %1;" :: "l"(g_cnt_ue + d), "r"(1) : "memory");
}

__global__ void agg_se_kernel(const int* __restrict__ src, const int* __restrict__ dst,
                              const float* __restrict__ x_sender, int nE) {
    int e = blockIdx.x * blockDim.x + threadIdx.x;
    if (e >= nE) return;
    int d = dst[e];
    float v = x_sender[src[e]];
    asm volatile("red.global.add.f32 [%0], %1;" :: "l"(g_sum1 + d), "f"(v) : "memory");
    asm volatile("red.global.add.s32 [%0], %1;" :: "l"(g_cnt_se + d), "r"(1) : "memory");
}

// ---------------- qprep: per-row rank-11 vector into A' cols 256..287 -------
__global__ void qprep_kernel() {
    int r = blockIdx.x * 256 + threadIdx.x;
    if (r >= NE) return;
    float q[16];
#pragma unroll
    for (int i = 0; i < 16; i++) q[i] = 0.f;
    int cu = g_cnt_ue[r];
    if (cu > 0) {
        float inv = 1.f / (float)cu;
#pragma unroll
        for (int c = 0; c < 8; c++) q[c] = g_sum8[(size_t)r * 8 + c] * inv;
        q[8] = 1.f;
    }
    int cs = g_cnt_se[r];
    if (cs > 0) {
        q[9] = g_sum1[r] / (float)cs;
        q[10] = 1.f;
    }
    __nv_bfloat16* ph = g_AH + (size_t)r * KB1 + 256;
    __nv_bfloat16* pl = g_AL + (size_t)r * KB1 + 256;
#pragma unroll
    for (int i = 0; i < 16; i++) {
        __nv_bfloat16 h = __float2bfloat16(q[i]);
        ph[i] = h;
        pl[i] = __float2bfloat16(q[i] - __bfloat162float(h));
    }
    __nv_bfloat16 z = __float2bfloat16(0.f);
#pragma unroll
    for (int i = 16; i < 32; i++) { ph[i] = z; pl[i] = z; }
}

// ---------------- cp.async helpers ------------------------------------------
__device__ __forceinline__ void cp16(uint32_t d, const void* s, int sz) {
    asm volatile("cp.async.cg.shared.global [%0], [%1], 16, %2;"
                 :: "r"(d), "l"(s), "r"(sz));
}
#define CP_COMMIT() asm volatile("cp.async.commit_group;")
#define CP_WAIT0()  asm volatile("cp.async.wait_group 0;")

__device__ __forceinline__ void ldsm4(uint32_t addr, uint32_t& r0, uint32_t& r1,
                                      uint32_t& r2, uint32_t& r3) {
    asm volatile("ldmatrix.sync.aligned.m8n8.x4.shared.b16 {%0,%1,%2,%3}, [%4];"
                 : "=r"(r0), "=r"(r1), "=r"(r2), "=r"(r3) : "r"(addr));
}

__device__ __forceinline__ void mma16816(float* c, const uint32_t* a, uint32_t b0, uint32_t b1) {
    asm volatile("mma.sync.aligned.m16n8k16.row.col.f32.bf16.bf16.f32 "
                 "{%0,%1,%2,%3}, {%4,%5,%6,%7}, {%8,%9}, {%0,%1,%2,%3};"
                 : "+f"(c[0]), "+f"(c[1]), "+f"(c[2]), "+f"(c[3])
                 : "r"(a[0]), "r"(a[1]), "r"(a[2]), "r"(a[3]), "r"(b0), "r"(b1));
}

// ---------------- tensor-core split-bf16 GEMM (double-buffered) -------------
// MODE 0: C = x_email[50000,768] @ W_e^T + b_e -> split bf16 planes cols 0..255
// MODE 1: C = A'[50000,288] @ W'^T + bias2 -> 0.5, leaky, gated residual -> g_he
// SMEM plane = 128 rows * 40 halves = 5120 elems = 10240 B; 4 planes x 2 stages = 80 KB
template <int MODE>
__global__ __launch_bounds__(256) void gemm_tc(const float* __restrict__ A_ext,
                                               const float* __restrict__ bias_ext,
                                               const float* __restrict__ gate) {
    constexpr int KB = (MODE == 0) ? KD : KB1;
    constexpr int NK = KB / 32;
    const __nv_bfloat16* __restrict__ WH = (MODE == 0) ? g_WeH : g_WcH;
    const __nv_bfloat16* __restrict__ WL = (MODE == 0) ? g_WeL : g_WcL;
    const float* __restrict__ bias = (MODE == 0) ? bias_ext : g_bias2;

    extern __shared__ __nv_bfloat16 dsm[];
    const uint32_t sbase = (uint32_t)__cvta_generic_to_shared(dsm);

    const int tid = threadIdx.x;
    const int lane = tid & 31;
    const int warp = tid >> 5;
    const int wm = warp & 1;
    const int wn = warp >> 1;
    const int m0 = blockIdx.x * 128;
    const int n0 = blockIdx.y * 128;

    float C[4][4][4];
#pragma unroll
    for (int i = 0; i < 4; i++)
#pragma unroll
        for (int j = 0; j < 4; j++)
#pragma unroll
            for (int q = 0; q < 4; q++) C[i][j][q] = 0.f;

    const int a_row_off = ((lane >> 3) & 1) * 8 + (lane & 7);
    const int a_k_off   = ((lane >> 4) & 1) * 8;
    const int b_row_off = ((lane >> 4) & 1) * 8 + (lane & 7);
    const int b_k_off   = ((lane >> 3) & 1) * 8;

    float4 Ar[4];   // MODE 0 register-prefetch

    // ---- stage issue: cp.async B (and A for MODE 1) for k-tile kt into buffer buf
    auto issue_stage = [&](int kt, int buf) {
        const int k0 = kt * 32;
        uint32_t bhB = sbase + (uint32_t)(buf * 4 + 2) * 10240u;
        uint32_t blB = sbase + (uint32_t)(buf * 4 + 3) * 10240u;
#pragma unroll
        for (int i = 0; i < 2; i++) {
            int f = tid + i * 256;
            int row = f >> 2, m = f & 3;
            size_t go = (size_t)(n0 + row) * KB + k0 + m * 8;
            uint32_t so = (uint32_t)(row * 40 + m * 8) * 2;
            cp16(bhB + so, WH + go, 16);
            cp16(blB + so, WL + go, 16);
        }
        if (MODE == 1) {
            uint32_t ahB = sbase + (uint32_t)(buf * 4 + 0) * 10240u;
            uint32_t alB = sbase + (uint32_t)(buf * 4 + 1) * 10240u;
#pragma unroll
            for (int i = 0; i < 2; i++) {
                int f = tid + i * 256;
                int row = f >> 2, m = f & 3;
                bool v = (m0 + row) < NE;
                size_t rr = v ? (size_t)(m0 + row) : 0;
                size_t go = rr * KB1 + k0 + m * 8;
                uint32_t so = (uint32_t)(row * 40 + m * 8) * 2;
                cp16(ahB + so, g_AH + go, v ? 16 : 0);
                cp16(alB + so, g_AL + go, v ? 16 : 0);
            }
        }
        CP_COMMIT();
    };

    auto loadA = [&](int kt) {   // MODE 0 only
        const int k0 = kt * 32;
#pragma unroll
        for (int i = 0; i < 4; i++) {
            int f = tid + i * 256;
            int row = f >> 3, c4 = (f & 7) << 2;
            int gr = m0 + row;
            Ar[i] = (gr < NE) ? *(const float4*)(A_ext + (size_t)gr * KD + k0 + c4)
                              : make_float4(0.f, 0.f, 0.f, 0.f);
        }
    };

    auto storeA = [&](int buf) {  // MODE 0 only: split + store to smem
        __nv_bfloat16* Ah = dsm + (size_t)(buf * 4 + 0) * 5120;
        __nv_bfloat16* Al = dsm + (size_t)(buf * 4 + 1) * 5120;
#pragma unroll
        for (int i = 0; i < 4; i++) {
            int f = tid + i * 256;
            int row = f >> 3, c4 = (f & 7) << 2;
            float4 v = Ar[i];
            __nv_bfloat16 h0 = __float2bfloat16(v.x);
            __nv_bfloat16 h1 = __float2bfloat16(v.y);
            __nv_bfloat16 h2 = __float2bfloat16(v.z);
            __nv_bfloat16 h3 = __float2bfloat16(v.w);
            __nv_bfloat162 hp0; hp0.x = h0; hp0.y = h1;
            __nv_bfloat162 hp1; hp1.x = h2; hp1.y = h3;
            __nv_bfloat162 lp0; lp0.x = __float2bfloat16(v.x - __bfloat162float(h0));
                                lp0.y = __float2bfloat16(v.y - __bfloat162float(h1));
            __nv_bfloat162 lp1; lp1.x = __float2bfloat16(v.z - __bfloat162float(h2));
                                lp1.y = __float2bfloat16(v.w - __bfloat162float(h3));
            *(__nv_bfloat162*)(Ah + row * 40 + c4)     = hp0;
            *(__nv_bfloat162*)(Ah + row * 40 + c4 + 2) = hp1;
            *(__nv_bfloat162*)(Al + row * 40 + c4)     = lp0;
            *(__nv_bfloat162*)(Al + row * 40 + c4 + 2) = lp1;
        }
    };

    // ---- prologue
    if (MODE == 0) loadA(0);
    issue_stage(0, 0);

    // ---- mainloop
    for (int kt = 0; kt < NK; kt++) {
        const int cur = kt & 1;
        if (MODE == 0) storeA(cur);
        CP_WAIT0();
        __syncthreads();
        if (kt + 1 < NK) {
            issue_stage(kt + 1, cur ^ 1);
            if (MODE == 0) loadA(kt + 1);
        }

        const uint32_t sAh = sbase + (uint32_t)(cur * 4 + 0) * 10240u;
        const uint32_t sAl = sbase + (uint32_t)(cur * 4 + 1) * 10240u;
        const uint32_t sBh = sbase + (uint32_t)(cur * 4 + 2) * 10240u;
        const uint32_t sBl = sbase + (uint32_t)(cur * 4 + 3) * 10240u;

#pragma unroll
        for (int kh = 0; kh < 2; kh++) {
            uint32_t Af_h[4][4];
            uint32_t Af_l[4][4];
#pragma unroll
            for (int mf = 0; mf < 4; mf++) {
                int row = wm * 64 + mf * 16 + a_row_off;
                uint32_t off = (uint32_t)(row * 40 + kh * 16 + a_k_off) * 2;
                ldsm4(sAh + off, Af_h[mf][0], Af_h[mf][1], Af_h[mf][2], Af_h[mf][3]);
                ldsm4(sAl + off, Af_l[mf][0], Af_l[mf][1], Af_l[mf][2], Af_l[mf][3]);
            }
            uint32_t Bf_h[2][4];
            uint32_t Bf_l[2][4];
#pragma unroll
            for (int nf = 0; nf < 2; nf++) {
                int row = wn * 32 + nf * 16 + b_row_off;
                uint32_t off = (uint32_t)(row * 40 + kh * 16 + b_k_off) * 2;
                ldsm4(sBh + off, Bf_h[nf][0], Bf_h[nf][1], Bf_h[nf][2], Bf_h[nf][3]);
                ldsm4(sBl + off, Bf_l[nf][0], Bf_l[nf][1], Bf_l[nf][2], Bf_l[nf][3]);
            }
#pragma unroll
            for (int mf = 0; mf < 4; mf++) {
#pragma unroll
                for (int j = 0; j < 4; j++) {
                    int nf = j >> 1;
                    int hh = j & 1;
                    uint32_t bh0 = Bf_h[nf][hh * 2];
                    uint32_t bh1 = Bf_h[nf][hh * 2 + 1];
                    uint32_t bl0 = Bf_l[nf][hh * 2];
                    uint32_t bl1 = Bf_l[nf][hh * 2 + 1];
                    mma16816(C[mf][j], Af_h[mf], bh0, bh1);
                    mma16816(C[mf][j], Af_h[mf], bl0, bl1);
                    mma16816(C[mf][j], Af_l[mf], bh0, bh1);
                }
            }
        }
    }

    // ---- epilogue
    float alpha = 0.f;
    if (MODE == 1) alpha = 1.f / (1.f + expf(-gate[0]));
    const int g = lane >> 2, t = lane & 3;

#pragma unroll
    for (int mf = 0; mf < 4; mf++) {
        int r0 = m0 + wm * 64 + mf * 16 + g;
#pragma unroll
        for (int j = 0; j < 4; j++) {
            int col = n0 + wn * 32 + j * 8 + t * 2;
            float b0 = bias[col], b1 = bias[col + 1];
#pragma unroll
            for (int half = 0; half < 2; half++) {
                int row = r0 + half * 8;
                if (row >= NE) continue;
                float v0 = C[mf][j][half * 2 + 0] + b0;
                float v1 = C[mf][j][half * 2 + 1] + b1;
                if (MODE == 0) {
                    __nv_bfloat16 h0 = __float2bfloat16(v0);
                    __nv_bfloat16 h1 = __float2bfloat16(v1);
                    __nv_bfloat162 hp; hp.x = h0; hp.y = h1;
                    __nv_bfloat162 lp;
                    lp.x = __float2bfloat16(v0 - __bfloat162float(h0));
                    lp.y = __float2bfloat16(v1 - __bfloat162float(h1));
                    *(__nv_bfloat162*)&g_AH[(size_t)row * KB1 + col] = hp;
                    *(__nv_bfloat162*)&g_AL[(size_t)row * KB1 + col] = lp;
                } else {
                    __nv_bfloat162 rh = *(const __nv_bfloat162*)&g_AH[(size_t)row * KB1 + col];
                    __nv_bfloat162 rl = *(const __nv_bfloat162*)&g_AL[(size_t)row * KB1 + col];
                    float rr0 = __bfloat162float(rh.x) + __bfloat162float(rl.x);
                    float rr1 = __bfloat162float(rh.y) + __bfloat162float(rl.y);
                    float u;
                    u = 0.5f * v0; u = u > 0.f ? u : 0.2f * u;
                    float o0 = alpha * u + (1.f - alpha) * rr0;
                    u = 0.5f * v1; u = u > 0.f ? u : 0.2f * u;
                    float o1 = alpha * u + (1.f - alpha) * rr1;
                    *(float2*)&g_he[(size_t)row * HD + col] = make_float2(o0, o1);
                }
            }
        }
    }
}

// ---------------- KAN classifier --------------------------------------------
__global__ __launch_bounds__(256) void kan_kernel(const float* __restrict__ base_w,
                                                  const float* __restrict__ spline_w,
                                                  float* __restrict__ out) {
    __shared__ float sbw[2 * 256];
    __shared__ float ssw[8 * 2 * 256];
    int tid = threadIdx.x;
    for (int i = tid; i < 512; i += 256) sbw[i] = base_w[i];
    for (int i = tid; i < 4096; i += 256) {
        int o = i >> 11;
        int h = (i >> 3) & 255;
        int g = i & 7;
        ssw[g * 512 + o * 256 + h] = spline_w[i];
    }
    __syncthreads();

    int warp = tid >> 5, lane = tid & 31;
    int base = blockIdx.x * 64;
    for (int nn = warp; nn < 64; nn += 8) {
        int n = base + nn;
        if (n >= NE) break;
        float acc0 = 0.f, acc1 = 0.f;
#pragma unroll
        for (int it = 0; it < 8; it++) {
            int h = it * 32 + lane;
            float x = g_he[(size_t)n * HD + h];
            float sil = x * __fdividef(1.f, 1.f + __expf(-x));
            acc0 += sil * sbw[h];
            acc1 += sil * sbw[256 + h];
            float b[11];
#pragma unroll
            for (int i = 0; i < 11; i++) {
                float g0 = -2.2f + 0.4f * (float)i;
                float g1 = g0 + 0.4f;
                b[i] = (x >= g0 && x < g1) ? 1.f : 0.f;
            }
#pragma unroll
            for (int p = 1; p <= 3; p++) {
                float inv = 1.f / (0.4f * (float)p);
#pragma unroll
                for (int i = 0; i < 11 - p; i++) {
                    float gi = -2.2f + 0.4f * (float)i;
                    float left = (x - gi) * inv;
                    float right = ((gi + 0.4f * (float)(p + 1)) - x) * inv;
                    b[i] = left * b[i] + right * b[i + 1];
                }
            }
#pragma unroll
            for (int g = 0; g < 8; g++) {
                acc0 += b[g] * ssw[g * 512 + h];
                acc1 += b[g] * ssw[g * 512 + 256 + h];
            }
        }
#pragma unroll
        for (int off = 16; off; off >>= 1) {
            acc0 += __shfl_xor_sync(0xffffffff, acc0, off);
            acc1 += __shfl_xor_sync(0xffffffff, acc1, off);
        }
        if (lane == 0) {
            out[n * 2 + 0] = acc0;
            out[n * 2 + 1] = acc1;
        }
    }
}

// ---------------- launch ----------------------------------------------------
extern "C" void kernel_launch(void* const* d_in, const int* in_sizes, int n_in,
                              void* d_out, int out_size) {
    const float* x_email   = (const float*)d_in[0];
    const float* x_url     = (const float*)d_in[1];
    const float* x_sender  = (const float*)d_in[2];
    const float* W_e       = (const float*)d_in[3];
    const float* b_e       = (const float*)d_in[4];
    const float* W_u       = (const float*)d_in[5];
    const float* b_u       = (const float*)d_in[6];
    const float* W_s       = (const float*)d_in[7];
    const float* b_s       = (const float*)d_in[8];
    const float* Wl_ue     = (const float*)d_in[12];
    const float* bl_ue     = (const float*)d_in[13];
    const float* Wr_ue     = (const float*)d_in[14];
    const float* Wl_se     = (const float*)d_in[15];
    const float* bl_se     = (const float*)d_in[16];
    const float* Wr_se     = (const float*)d_in[17];
    const float* gate      = (const float*)d_in[21];
    const float* kan_base  = (const float*)d_in[22];
    const float* kan_spline= (const float*)d_in[23];
    const int*   ue_src    = (const int*)d_in[26];
    const int*   ue_dst    = (const int*)d_in[27];
    const int*   se_src    = (const int*)d_in[28];
    const int*   se_dst    = (const int*)d_in[29];
    int n_ue = in_sizes[26];
    int n_se = in_sizes[28];
    float* out = (float*)d_out;

    cudaFuncSetAttribute((void*)gemm_tc<0>, cudaFuncAttributeMaxDynamicSharedMemorySize, 81920);
    cudaFuncSetAttribute((void*)gemm_tc<1>, cudaFuncAttributeMaxDynamicSharedMemorySize, 81920);

    dim3 ggrid((NE + 127) / 128, 2);

    zero_kernel<<<512, 256>>>();
    prep_kernel<<<KD, 256>>>(W_e, Wr_ue, Wr_se, bl_ue, bl_se);
    prep2_kernel<<<HD, 32>>>(Wl_ue, W_u, b_u, Wl_se, W_s, b_s);
    agg_ue_kernel<<<(n_ue + 255) / 256, 256>>>(ue_src, ue_dst, x_url, n_ue);
    agg_se_kernel<<<(n_se + 255) / 256, 256>>>(se_src, se_dst, x_sender, n_se);
    gemm_tc<0><<<ggrid, 256, 81920>>>(x_email, b_e, nullptr);
    qprep_kernel<<<(NE + 255) / 256, 256>>>();
    gemm_tc<1><<<ggrid, 256, 81920>>>(nullptr, nullptr, gate);
    kan_kernel<<<(NE + 63) / 64, 256>>>(kan_base, kan_spline, out);
}

// round 6
// speedup vs baseline: 3.4284x; 1.3851x over previous
#include <cuda_runtime.h>
#include <cuda_fp16.h>
#include <stdint.h>
#include <math.h>

#define NE 50000
#define HD 256
#define KD 768
#define KB1 288   // gemm1 K: 256 he + 32 q (11 real + pad)

// ---------------- scratch (static __device__, no allocations) ----------------
__device__ __half g_AH[(size_t)NE * KB1];  // A' hi plane [NE][288]
__device__ __half g_AL[(size_t)NE * KB1];  // A' lo plane
__device__ float g_he[(size_t)NE * HD];    // final he (fp32, feeds KAN)
__device__ __half g_WeH[HD * KD];          // W_e hi [n][k] k<768
__device__ __half g_WeL[HD * KD];
__device__ __half g_WcH[HD * KB1];         // W' hi [n][k] k<288
__device__ __half g_WcL[HD * KB1];
__device__ float g_bias2[HD];              // bl_ue + bl_se
__device__ float g_sum8[NE * 8];
__device__ float g_sum1[NE];
__device__ int   g_cnt_ue[NE];
__device__ int   g_cnt_se[NE];

// ---------------- zero accumulators (re-zeroed every graph replay) ----------
__global__ void zero_kernel() {
    int i = blockIdx.x * blockDim.x + threadIdx.x;
    int stride = gridDim.x * blockDim.x;
    for (int j = i; j < NE * 8; j += stride) g_sum8[j] = 0.f;
    for (int j = i; j < NE; j += stride) { g_sum1[j] = 0.f; g_cnt_ue[j] = 0; g_cnt_se[j] = 0; }
}

// ---------------- weight prep: split fp32 -> fp16 hi/lo ---------------------
__global__ void prep_kernel(const float* __restrict__ W_e,
                            const float* __restrict__ Wr_ue, const float* __restrict__ Wr_se,
                            const float* __restrict__ bl_ue, const float* __restrict__ bl_se) {
    int idx = blockIdx.x * 256 + threadIdx.x;   // 768 blocks: covers 256*768
    if (idx < HD) g_bias2[idx] = bl_ue[idx] + bl_se[idx];
    float we = W_e[idx];
    __half h = __float2half_rn(we);
    g_WeH[idx] = h;
    g_WeL[idx] = __float2half_rn(we - __half2float(h));
    if (idx < HD * HD) {
        int n = idx >> 8, k = idx & 255;
        float w = Wr_ue[idx] + Wr_se[idx];
        __half wh = __float2half_rn(w);
        g_WcH[n * KB1 + k] = wh;
        g_WcL[n * KB1 + k] = __float2half_rn(w - __half2float(wh));
    }
}

// ---------------- prep2: rank-11 correction columns of W' -------------------
__global__ void prep2_kernel(const float* __restrict__ Wl_ue, const float* __restrict__ W_u,
                             const float* __restrict__ b_u,
                             const float* __restrict__ Wl_se, const float* __restrict__ W_s,
                             const float* __restrict__ b_s) {
    int n = blockIdx.x;
    int c = threadIdx.x;    // 0..31
    float acc = 0.f;
    if (c < 8) {
        for (int h = 0; h < HD; h++) acc += Wl_ue[n * HD + h] * W_u[h * 8 + c];
    } else if (c == 8) {
        for (int h = 0; h < HD; h++) acc += Wl_ue[n * HD + h] * b_u[h];
    } else if (c == 9) {
        for (int h = 0; h < HD; h++) acc += Wl_se[n * HD + h] * W_s[h];
    } else if (c == 10) {
        for (int h = 0; h < HD; h++) acc += Wl_se[n * HD + h] * b_s[h];
    }
    __half h = __float2half_rn(acc);
    g_WcH[n * KB1 + 256 + c] = h;
    g_WcL[n * KB1 + 256 + c] = __float2half_rn(acc - __half2float(h));
}

// ---------------- edge aggregation ------------------------------------------
__global__ void agg_ue_kernel(const int* __restrict__ src, const int* __restrict__ dst,
                              const float* __restrict__ x_url, int nE) {
    int e = blockIdx.x * blockDim.x + threadIdx.x;
    if (e >= nE) return;
    int s = src[e], d = dst[e];
    const float4* xu = (const float4*)(x_url + (size_t)s * 8);
    float4 a = xu[0], b = xu[1];
    float* p = g_sum8 + (size_t)d * 8;
    asm volatile("red.global.add.v4.f32 [%0], {%1,%2,%3,%4};"
                 :: "l"(p), "f"(a.x), "f"(a.y), "f"(a.z), "f"(a.w) : "memory");
    asm volatile("red.global.add.v4.f32 [%0], {%1,%2,%3,%4};"
                 :: "l"(p + 4), "f"(b.x), "f"(b.y), "f"(b.z), "f"(b.w) : "memory");
    asm volatile("red.global.add.s32 [%0], %1;" :: "l"(g_cnt_ue + d), "r"(1) : "memory");
}

__global__ void agg_se_kernel(const int* __restrict__ src, const int* __restrict__ dst,
                              const float* __restrict__ x_sender, int nE) {
    int e = blockIdx.x * blockDim.x + threadIdx.x;
    if (e >= nE) return;
    int d = dst[e];
    float v = x_sender[src[e]];
    asm volatile("red.global.add.f32 [%0], %1;" :: "l"(g_sum1 + d), "f"(v) : "memory");
    asm volatile("red.global.add.s32 [%0], %1;" :: "l"(g_cnt_se + d), "r"(1) : "memory");
}

// ---------------- qprep: per-row rank-11 vector into A' cols 256..287 -------
__global__ void qprep_kernel() {
    int r = blockIdx.x * 256 + threadIdx.x;
    if (r >= NE) return;
    float q[16];
#pragma unroll
    for (int i = 0; i < 16; i++) q[i] = 0.f;
    int cu = g_cnt_ue[r];
    if (cu > 0) {
        float inv = 1.f / (float)cu;
#pragma unroll
        for (int c = 0; c < 8; c++) q[c] = g_sum8[(size_t)r * 8 + c] * inv;
        q[8] = 1.f;
    }
    int cs = g_cnt_se[r];
    if (cs > 0) {
        q[9] = g_sum1[r] / (float)cs;
        q[10] = 1.f;
    }
    __half* ph = g_AH + (size_t)r * KB1 + 256;
    __half* pl = g_AL + (size_t)r * KB1 + 256;
#pragma unroll
    for (int i = 0; i < 16; i++) {
        __half h = __float2half_rn(q[i]);
        ph[i] = h;
        pl[i] = __float2half_rn(q[i] - __half2float(h));
    }
    __half z = __float2half_rn(0.f);
#pragma unroll
    for (int i = 16; i < 32; i++) { ph[i] = z; pl[i] = z; }
}

// ---------------- cp.async helpers ------------------------------------------
__device__ __forceinline__ void cp16(uint32_t d, const void* s, int sz) {
    asm volatile("cp.async.cg.shared.global [%0], [%1], 16, %2;"
                 :: "r"(d), "l"(s), "r"(sz));
}
#define CP_COMMIT() asm volatile("cp.async.commit_group;")
#define CP_WAIT0()  asm volatile("cp.async.wait_group 0;")

__device__ __forceinline__ void ldsm4(uint32_t addr, uint32_t& r0, uint32_t& r1,
                                      uint32_t& r2, uint32_t& r3) {
    asm volatile("ldmatrix.sync.aligned.m8n8.x4.shared.b16 {%0,%1,%2,%3}, [%4];"
                 : "=r"(r0), "=r"(r1), "=r"(r2), "=r"(r3) : "r"(addr));
}

__device__ __forceinline__ void mma16816(float* c, const uint32_t* a, uint32_t b0, uint32_t b1) {
    asm volatile("mma.sync.aligned.m16n8k16.row.col.f32.f16.f16.f32 "
                 "{%0,%1,%2,%3}, {%4,%5,%6,%7}, {%8,%9}, {%0,%1,%2,%3};"
                 : "+f"(c[0]), "+f"(c[1]), "+f"(c[2]), "+f"(c[3])
                 : "r"(a[0]), "r"(a[1]), "r"(a[2]), "r"(a[3]), "r"(b0), "r"(b1));
}

// ---------------- tensor-core split-fp16 GEMM (double-buffered) -------------
// MODE 0: C = x_email[50000,768] @ W_e^T + b_e -> split fp16 planes cols 0..255
//         A hi-only (dropped Al*Bh term, ~1.4e-4 rms): planes per stage = {Ah, Bh, Bl}
// MODE 1: C = A'[50000,288] @ W'^T + bias2 -> 0.5, leaky, gated residual -> g_he
//         full 3-term split: planes per stage = {Ah, Al, Bh, Bl}
// plane = 128 rows * 40 halves = 10240 B
template <int MODE>
__global__ __launch_bounds__(256) void gemm_tc(const float* __restrict__ A_ext,
                                               const float* __restrict__ bias_ext,
                                               const float* __restrict__ gate) {
    constexpr int KB = (MODE == 0) ? KD : KB1;
    constexpr int NK = KB / 32;
    constexpr int PLANES = (MODE == 0) ? 3 : 4;
    constexpr int P_AH = 0;
    constexpr int P_AL = 1;                       // MODE 1 only
    constexpr int P_BH = (MODE == 0) ? 1 : 2;
    constexpr int P_BL = (MODE == 0) ? 2 : 3;
    const __half* __restrict__ WH = (MODE == 0) ? g_WeH : g_WcH;
    const __half* __restrict__ WL = (MODE == 0) ? g_WeL : g_WcL;
    const float* __restrict__ bias = (MODE == 0) ? bias_ext : g_bias2;

    extern __shared__ __half dsm[];
    const uint32_t sbase = (uint32_t)__cvta_generic_to_shared(dsm);

    const int tid = threadIdx.x;
    const int lane = tid & 31;
    const int warp = tid >> 5;
    const int wm = warp & 1;
    const int wn = warp >> 1;
    const int m0 = blockIdx.x * 128;
    const int n0 = blockIdx.y * 128;

    float C[4][4][4];
#pragma unroll
    for (int i = 0; i < 4; i++)
#pragma unroll
        for (int j = 0; j < 4; j++)
#pragma unroll
            for (int q = 0; q < 4; q++) C[i][j][q] = 0.f;

    const int a_row_off = ((lane >> 3) & 1) * 8 + (lane & 7);
    const int a_k_off   = ((lane >> 4) & 1) * 8;
    const int b_row_off = ((lane >> 4) & 1) * 8 + (lane & 7);
    const int b_k_off   = ((lane >> 3) & 1) * 8;

    float4 Ar[4];   // MODE 0 register-prefetch

    auto issue_stage = [&](int kt, int buf) {
        const int k0 = kt * 32;
        uint32_t bhB = sbase + (uint32_t)(buf * PLANES + P_BH) * 10240u;
        uint32_t blB = sbase + (uint32_t)(buf * PLANES + P_BL) * 10240u;
#pragma unroll
        for (int i = 0; i < 2; i++) {
            int f = tid + i * 256;
            int row = f >> 2, m = f & 3;
            size_t go = (size_t)(n0 + row) * KB + k0 + m * 8;
            uint32_t so = (uint32_t)(row * 40 + m * 8) * 2;
            cp16(bhB + so, WH + go, 16);
            cp16(blB + so, WL + go, 16);
        }
        if (MODE == 1) {
            uint32_t ahB = sbase + (uint32_t)(buf * PLANES + P_AH) * 10240u;
            uint32_t alB = sbase + (uint32_t)(buf * PLANES + P_AL) * 10240u;
#pragma unroll
            for (int i = 0; i < 2; i++) {
                int f = tid + i * 256;
                int row = f >> 2, m = f & 3;
                bool v = (m0 + row) < NE;
                size_t rr = v ? (size_t)(m0 + row) : 0;
                size_t go = rr * KB1 + k0 + m * 8;
                uint32_t so = (uint32_t)(row * 40 + m * 8) * 2;
                cp16(ahB + so, g_AH + go, v ? 16 : 0);
                cp16(alB + so, g_AL + go, v ? 16 : 0);
            }
        }
        CP_COMMIT();
    };

    auto loadA = [&](int kt) {   // MODE 0 only
        const int k0 = kt * 32;
#pragma unroll
        for (int i = 0; i < 4; i++) {
            int f = tid + i * 256;
            int row = f >> 3, c4 = (f & 7) << 2;
            int gr = m0 + row;
            Ar[i] = (gr < NE) ? *(const float4*)(A_ext + (size_t)gr * KD + k0 + c4)
                              : make_float4(0.f, 0.f, 0.f, 0.f);
        }
    };

    auto storeA = [&](int buf) {  // MODE 0 only: hi-plane only
        __half* Ah = dsm + (size_t)(buf * PLANES + P_AH) * 5120;
#pragma unroll
        for (int i = 0; i < 4; i++) {
            int f = tid + i * 256;
            int row = f >> 3, c4 = (f & 7) << 2;
            float4 v = Ar[i];
            __half2 hp0; hp0.x = __float2half_rn(v.x); hp0.y = __float2half_rn(v.y);
            __half2 hp1; hp1.x = __float2half_rn(v.z); hp1.y = __float2half_rn(v.w);
            *(__half2*)(Ah + row * 40 + c4)     = hp0;
            *(__half2*)(Ah + row * 40 + c4 + 2) = hp1;
        }
    };

    // ---- prologue
    if (MODE == 0) loadA(0);
    issue_stage(0, 0);

    // ---- mainloop
    for (int kt = 0; kt < NK; kt++) {
        const int cur = kt & 1;
        if (MODE == 0) storeA(cur);
        CP_WAIT0();
        __syncthreads();
        if (kt + 1 < NK) {
            issue_stage(kt + 1, cur ^ 1);
            if (MODE == 0) loadA(kt + 1);
        }

        const uint32_t sAh = sbase + (uint32_t)(cur * PLANES + P_AH) * 10240u;
        const uint32_t sAl = sbase + (uint32_t)(cur * PLANES + P_AL) * 10240u;
        const uint32_t sBh = sbase + (uint32_t)(cur * PLANES + P_BH) * 10240u;
        const uint32_t sBl = sbase + (uint32_t)(cur * PLANES + P_BL) * 10240u;

#pragma unroll
        for (int kh = 0; kh < 2; kh++) {
            uint32_t Af_h[4][4];
            uint32_t Af_l[4][4];
#pragma unroll
            for (int mf = 0; mf < 4; mf++) {
                int row = wm * 64 + mf * 16 + a_row_off;
                uint32_t off = (uint32_t)(row * 40 + kh * 16 + a_k_off) * 2;
                ldsm4(sAh + off, Af_h[mf][0], Af_h[mf][1], Af_h[mf][2], Af_h[mf][3]);
                if (MODE == 1)
                    ldsm4(sAl + off, Af_l[mf][0], Af_l[mf][1], Af_l[mf][2], Af_l[mf][3]);
            }
            uint32_t Bf_h[2][4];
            uint32_t Bf_l[2][4];
#pragma unroll
            for (int nf = 0; nf < 2; nf++) {
                int row = wn * 32 + nf * 16 + b_row_off;
                uint32_t off = (uint32_t)(row * 40 + kh * 16 + b_k_off) * 2;
                ldsm4(sBh + off, Bf_h[nf][0], Bf_h[nf][1], Bf_h[nf][2], Bf_h[nf][3]);
                ldsm4(sBl + off, Bf_l[nf][0], Bf_l[nf][1], Bf_l[nf][2], Bf_l[nf][3]);
            }
#pragma unroll
            for (int mf = 0; mf < 4; mf++) {
#pragma unroll
                for (int j = 0; j < 4; j++) {
                    int nf = j >> 1;
                    int hh = j & 1;
                    uint32_t bh0 = Bf_h[nf][hh * 2];
                    uint32_t bh1 = Bf_h[nf][hh * 2 + 1];
                    uint32_t bl0 = Bf_l[nf][hh * 2];
                    uint32_t bl1 = Bf_l[nf][hh * 2 + 1];
                    mma16816(C[mf][j], Af_h[mf], bh0, bh1);
                    mma16816(C[mf][j], Af_h[mf], bl0, bl1);
                    if (MODE == 1)
                        mma16816(C[mf][j], Af_l[mf], bh0, bh1);
                }
            }
        }
    }

    // ---- epilogue
    float alpha = 0.f;
    if (MODE == 1) alpha = 1.f / (1.f + expf(-gate[0]));
    const int g = lane >> 2, t = lane & 3;

#pragma unroll
    for (int mf = 0; mf < 4; mf++) {
        int r0 = m0 + wm * 64 + mf * 16 + g;
#pragma unroll
        for (int j = 0; j < 4; j++) {
            int col = n0 + wn * 32 + j * 8 + t * 2;
            float b0 = bias[col], b1 = bias[col + 1];
#pragma unroll
            for (int half = 0; half < 2; half++) {
                int row = r0 + half * 8;
                if (row >= NE) continue;
                float v0 = C[mf][j][half * 2 + 0] + b0;
                float v1 = C[mf][j][half * 2 + 1] + b1;
                if (MODE == 0) {
                    __half h0 = __float2half_rn(v0);
                    __half h1 = __float2half_rn(v1);
                    __half2 hp; hp.x = h0; hp.y = h1;
                    __half2 lp;
                    lp.x = __float2half_rn(v0 - __half2float(h0));
                    lp.y = __float2half_rn(v1 - __half2float(h1));
                    *(__half2*)&g_AH[(size_t)row * KB1 + col] = hp;
                    *(__half2*)&g_AL[(size_t)row * KB1 + col] = lp;
                } else {
                    __half2 rh = *(const __half2*)&g_AH[(size_t)row * KB1 + col];
                    __half2 rl = *(const __half2*)&g_AL[(size_t)row * KB1 + col];
                    float rr0 = __half2float(rh.x) + __half2float(rl.x);
                    float rr1 = __half2float(rh.y) + __half2float(rl.y);
                    float u;
                    u = 0.5f * v0; u = u > 0.f ? u : 0.2f * u;
                    float o0 = alpha * u + (1.f - alpha) * rr0;
                    u = 0.5f * v1; u = u > 0.f ? u : 0.2f * u;
                    float o1 = alpha * u + (1.f - alpha) * rr1;
                    *(float2*)&g_he[(size_t)row * HD + col] = make_float2(o0, o1);
                }
            }
        }
    }
}

// ---------------- KAN classifier: SiLU base + closed-form cubic B-spline ----
__global__ __launch_bounds__(256) void kan_kernel(const float* __restrict__ base_w,
                                                  const float* __restrict__ spline_w,
                                                  float* __restrict__ out) {
    __shared__ float sbw[2 * 256];
    __shared__ float ssw[8 * 2 * 256];   // [g][o][h]
    int tid = threadIdx.x;
    for (int i = tid; i < 512; i += 256) sbw[i] = base_w[i];
    for (int i = tid; i < 4096; i += 256) {
        int o = i >> 11;
        int h = (i >> 3) & 255;
        int g = i & 7;
        ssw[g * 512 + o * 256 + h] = spline_w[i];
    }
    __syncthreads();

    const float c6 = 1.f / 6.f;
    int warp = tid >> 5, lane = tid & 31;
    int base = blockIdx.x * 64;
    for (int nn = warp; nn < 64; nn += 8) {
        int n = base + nn;
        if (n >= NE) break;
        float acc0 = 0.f, acc1 = 0.f;
#pragma unroll
        for (int it = 0; it < 8; it++) {
            int h = it * 32 + lane;
            float x = g_he[(size_t)n * HD + h];
            float sil = x * __fdividef(1.f, 1.f + __expf(-x));
            acc0 += sil * sbw[h];
            acc1 += sil * sbw[256 + h];
            // order-3 B-spline: 4 nonzero bases; interval j of uniform grid
            float tt = (x + 2.2f) * 2.5f;
            float fj = floorf(tt);
            int j = (int)fj;
            if (j >= 0 && j < 11) {
                float u = tt - fj;
                float u2 = u * u, u3 = u2 * u;
                float p0 = u3 * c6;                                   // basis g=j
                float p1 = (1.f + 3.f * (u + u2) - 3.f * u3) * c6;    // g=j-1
                float p2 = (4.f - 6.f * u2 + 3.f * u3) * c6;          // g=j-2
                float om = 1.f - u;
                float p3 = om * om * om * c6;                         // g=j-3
                if (j < 8) {
                    acc0 += p0 * ssw[j * 512 + h];
                    acc1 += p0 * ssw[j * 512 + 256 + h];
                }
                int g1 = j - 1;
                if (g1 >= 0 && g1 < 8) {
                    acc0 += p1 * ssw[g1 * 512 + h];
                    acc1 += p1 * ssw[g1 * 512 + 256 + h];
                }
                int g2 = j - 2;
                if (g2 >= 0 && g2 < 8) {
                    acc0 += p2 * ssw[g2 * 512 + h];
                    acc1 += p2 * ssw[g2 * 512 + 256 + h];
                }
                int g3 = j - 3;
                if (g3 >= 0) {
                    acc0 += p3 * ssw[g3 * 512 + h];
                    acc1 += p3 * ssw[g3 * 512 + 256 + h];
                }
            }
        }
#pragma unroll
        for (int off = 16; off; off >>= 1) {
            acc0 += __shfl_xor_sync(0xffffffff, acc0, off);
            acc1 += __shfl_xor_sync(0xffffffff, acc1, off);
        }
        if (lane == 0) {
            out[n * 2 + 0] = acc0;
            out[n * 2 + 1] = acc1;
        }
    }
}

// ---------------- launch ----------------------------------------------------
extern "C" void kernel_launch(void* const* d_in, const int* in_sizes, int n_in,
                              void* d_out, int out_size) {
    const float* x_email   = (const float*)d_in[0];
    const float* x_url     = (const float*)d_in[1];
    const float* x_sender  = (const float*)d_in[2];
    const float* W_e       = (const float*)d_in[3];
    const float* b_e       = (const float*)d_in[4];
    const float* W_u       = (const float*)d_in[5];
    const float* b_u       = (const float*)d_in[6];
    const float* W_s       = (const float*)d_in[7];
    const float* b_s       = (const float*)d_in[8];
    const float* Wl_ue     = (const float*)d_in[12];
    const float* bl_ue     = (const float*)d_in[13];
    const float* Wr_ue     = (const float*)d_in[14];
    const float* Wl_se     = (const float*)d_in[15];
    const float* bl_se     = (const float*)d_in[16];
    const float* Wr_se     = (const float*)d_in[17];
    const float* gate      = (const float*)d_in[21];
    const float* kan_base  = (const float*)d_in[22];
    const float* kan_spline= (const float*)d_in[23];
    const int*   ue_src    = (const int*)d_in[26];
    const int*   ue_dst    = (const int*)d_in[27];
    const int*   se_src    = (const int*)d_in[28];
    const int*   se_dst    = (const int*)d_in[29];
    int n_ue = in_sizes[26];
    int n_se = in_sizes[28];
    float* out = (float*)d_out;

    cudaFuncSetAttribute((void*)gemm_tc<0>, cudaFuncAttributeMaxDynamicSharedMemorySize, 81920);
    cudaFuncSetAttribute((void*)gemm_tc<1>, cudaFuncAttributeMaxDynamicSharedMemorySize, 81920);

    dim3 ggrid((NE + 127) / 128, 2);

    zero_kernel<<<512, 256>>>();
    prep_kernel<<<KD, 256>>>(W_e, Wr_ue, Wr_se, bl_ue, bl_se);
    prep2_kernel<<<HD, 32>>>(Wl_ue, W_u, b_u, Wl_se, W_s, b_s);
    agg_ue_kernel<<<(n_ue + 255) / 256, 256>>>(ue_src, ue_dst, x_url, n_ue);
    agg_se_kernel<<<(n_se + 255) / 256, 256>>>(se_src, se_dst, x_sender, n_se);
    gemm_tc<0><<<ggrid, 256, 61440>>>(x_email, b_e, nullptr);
    qprep_kernel<<<(NE + 255) / 256, 256>>>();
    gemm_tc<1><<<ggrid, 256, 81920>>>(nullptr, nullptr, gate);
    kan_kernel<<<(NE + 63) / 64, 256>>>(kan_base, kan_spline, out);
}

// round 7
// speedup vs baseline: 4.0522x; 1.1819x over previous
#include <cuda_runtime.h>
#include <cuda_fp16.h>
#include <stdint.h>
#include <math.h>

#define NE 50000
#define HD 256
#define KD 768
#define KB1 288   // gemm1 K: 256 he + 32 q (11 real + pad)

// ---------------- scratch (static __device__, no allocations) ----------------
__device__ __half g_AH[(size_t)NE * KB1];  // A' hi plane [NE][288]
__device__ __half g_AL[(size_t)NE * KB1];  // A' lo plane (residual only, cols 0..255)
__device__ float g_he[(size_t)NE * HD];    // final he (fp32, feeds KAN)
__device__ __half g_WeH[HD * KD];          // W_e hi [n][k] k<768
__device__ __half g_WcH[HD * KB1];         // W' hi [n][k] k<288
__device__ __half g_WcL[HD * KB1];
__device__ float g_bias2[HD];              // bl_ue + bl_se
__device__ float g_sum8[NE * 8];
__device__ float g_sum1[NE];
__device__ int   g_cnt_ue[NE];
__device__ int   g_cnt_se[NE];

// ---------------- zero accumulators (re-zeroed every graph replay) ----------
__global__ void zero_kernel() {
    int i = blockIdx.x * blockDim.x + threadIdx.x;
    int stride = gridDim.x * blockDim.x;
    for (int j = i; j < NE * 8; j += stride) g_sum8[j] = 0.f;
    for (int j = i; j < NE; j += stride) { g_sum1[j] = 0.f; g_cnt_ue[j] = 0; g_cnt_se[j] = 0; }
}

// ---------------- weight prep ------------------------------------------------
__global__ void prep_kernel(const float* __restrict__ W_e,
                            const float* __restrict__ Wr_ue, const float* __restrict__ Wr_se,
                            const float* __restrict__ bl_ue, const float* __restrict__ bl_se) {
    int idx = blockIdx.x * 256 + threadIdx.x;   // 768 blocks: covers 256*768
    if (idx < HD) g_bias2[idx] = bl_ue[idx] + bl_se[idx];
    g_WeH[idx] = __float2half_rn(W_e[idx]);
    if (idx < HD * HD) {
        int n = idx >> 8, k = idx & 255;
        float w = Wr_ue[idx] + Wr_se[idx];
        __half wh = __float2half_rn(w);
        g_WcH[n * KB1 + k] = wh;
        g_WcL[n * KB1 + k] = __float2half_rn(w - __half2float(wh));
    }
}

// ---------------- prep2: rank-11 correction columns of W' -------------------
__global__ void prep2_kernel(const float* __restrict__ Wl_ue, const float* __restrict__ W_u,
                             const float* __restrict__ b_u,
                             const float* __restrict__ Wl_se, const float* __restrict__ W_s,
                             const float* __restrict__ b_s) {
    int n = blockIdx.x;
    int c = threadIdx.x;    // 0..31
    float acc = 0.f;
    if (c < 8) {
        for (int h = 0; h < HD; h++) acc += Wl_ue[n * HD + h] * W_u[h * 8 + c];
    } else if (c == 8) {
        for (int h = 0; h < HD; h++) acc += Wl_ue[n * HD + h] * b_u[h];
    } else if (c == 9) {
        for (int h = 0; h < HD; h++) acc += Wl_se[n * HD + h] * W_s[h];
    } else if (c == 10) {
        for (int h = 0; h < HD; h++) acc += Wl_se[n * HD + h] * b_s[h];
    }
    __half h = __float2half_rn(acc);
    g_WcH[n * KB1 + 256 + c] = h;
    g_WcL[n * KB1 + 256 + c] = __float2half_rn(acc - __half2float(h));
}

// ---------------- edge aggregation ------------------------------------------
__global__ void agg_ue_kernel(const int* __restrict__ src, const int* __restrict__ dst,
                              const float* __restrict__ x_url, int nE) {
    int e = blockIdx.x * blockDim.x + threadIdx.x;
    if (e >= nE) return;
    int s = src[e], d = dst[e];
    const float4* xu = (const float4*)(x_url + (size_t)s * 8);
    float4 a = xu[0], b = xu[1];
    float* p = g_sum8 + (size_t)d * 8;
    asm volatile("red.global.add.v4.f32 [%0], {%1,%2,%3,%4};"
                 :: "l"(p), "f"(a.x), "f"(a.y), "f"(a.z), "f"(a.w) : "memory");
    asm volatile("red.global.add.v4.f32 [%0], {%1,%2,%3,%4};"
                 :: "l"(p + 4), "f"(b.x), "f"(b.y), "f"(b.z), "f"(b.w) : "memory");
    asm volatile("red.global.add.s32 [%0], %1;" :: "l"(g_cnt_ue + d), "r"(1) : "memory");
}

__global__ void agg_se_kernel(const int* __restrict__ src, const int* __restrict__ dst,
                              const float* __restrict__ x_sender, int nE) {
    int e = blockIdx.x * blockDim.x + threadIdx.x;
    if (e >= nE) return;
    int d = dst[e];
    float v = x_sender[src[e]];
    asm volatile("red.global.add.f32 [%0], %1;" :: "l"(g_sum1 + d), "f"(v) : "memory");
    asm volatile("red.global.add.s32 [%0], %1;" :: "l"(g_cnt_se + d), "r"(1) : "memory");
}

// ---------------- qprep: per-row rank-11 vector into A' hi cols 256..287 ----
__global__ void qprep_kernel() {
    int r = blockIdx.x * 256 + threadIdx.x;
    if (r >= NE) return;
    float q[16];
#pragma unroll
    for (int i = 0; i < 16; i++) q[i] = 0.f;
    int cu = g_cnt_ue[r];
    if (cu > 0) {
        float inv = 1.f / (float)cu;
#pragma unroll
        for (int c = 0; c < 8; c++) q[c] = g_sum8[(size_t)r * 8 + c] * inv;
        q[8] = 1.f;
    }
    int cs = g_cnt_se[r];
    if (cs > 0) {
        q[9] = g_sum1[r] / (float)cs;
        q[10] = 1.f;
    }
    __half* ph = g_AH + (size_t)r * KB1 + 256;
    __half z = __float2half_rn(0.f);
#pragma unroll
    for (int i = 0; i < 16; i++) ph[i] = __float2half_rn(q[i]);
#pragma unroll
    for (int i = 16; i < 32; i++) ph[i] = z;
}

// ---------------- cp.async helpers ------------------------------------------
__device__ __forceinline__ void cp16(uint32_t d, const void* s, int sz) {
    asm volatile("cp.async.cg.shared.global [%0], [%1], 16, %2;"
                 :: "r"(d), "l"(s), "r"(sz));
}
#define CP_COMMIT() asm volatile("cp.async.commit_group;")
#define CP_WAIT0()  asm volatile("cp.async.wait_group 0;")

__device__ __forceinline__ void ldsm4(uint32_t addr, uint32_t& r0, uint32_t& r1,
                                      uint32_t& r2, uint32_t& r3) {
    asm volatile("ldmatrix.sync.aligned.m8n8.x4.shared.b16 {%0,%1,%2,%3}, [%4];"
                 : "=r"(r0), "=r"(r1), "=r"(r2), "=r"(r3) : "r"(addr));
}

__device__ __forceinline__ void mma16816(float* c, const uint32_t* a, uint32_t b0, uint32_t b1) {
    asm volatile("mma.sync.aligned.m16n8k16.row.col.f32.f16.f16.f32 "
                 "{%0,%1,%2,%3}, {%4,%5,%6,%7}, {%8,%9}, {%0,%1,%2,%3};"
                 : "+f"(c[0]), "+f"(c[1]), "+f"(c[2]), "+f"(c[3])
                 : "r"(a[0]), "r"(a[1]), "r"(a[2]), "r"(a[3]), "r"(b0), "r"(b1));
}

// ---------------- tensor-core fp16 GEMM (double-buffered) -------------------
// MODE 0: C = x_email @ W_e^T + b_e; 1 MMA (Ah*Bh); planes {Ah, Bh}
//         -> split fp16 hi/lo into g_AH/g_AL cols 0..255
// MODE 1: C = A'[50000,288] @ W'^T + bias2; 2 MMAs (Ah*Bh + Ah*Bl);
//         planes {Ah, Bh, Bl}; epilogue: 0.5, leaky, gated residual -> g_he
// plane = 128 rows * 40 halves = 10240 B
template <int MODE>
__global__ __launch_bounds__(256) void gemm_tc(const float* __restrict__ A_ext,
                                               const float* __restrict__ bias_ext,
                                               const float* __restrict__ gate) {
    constexpr int KB = (MODE == 0) ? KD : KB1;
    constexpr int NK = KB / 32;
    constexpr int PLANES = (MODE == 0) ? 2 : 3;
    constexpr int P_AH = 0;
    constexpr int P_BH = 1;
    constexpr int P_BL = 2;                       // MODE 1 only
    const __half* __restrict__ WH = (MODE == 0) ? g_WeH : g_WcH;
    const float* __restrict__ bias = (MODE == 0) ? bias_ext : g_bias2;

    extern __shared__ __half dsm[];
    const uint32_t sbase = (uint32_t)__cvta_generic_to_shared(dsm);

    const int tid = threadIdx.x;
    const int lane = tid & 31;
    const int warp = tid >> 5;
    const int wm = warp & 1;
    const int wn = warp >> 1;
    const int m0 = blockIdx.x * 128;
    const int n0 = blockIdx.y * 128;

    float C[4][4][4];
#pragma unroll
    for (int i = 0; i < 4; i++)
#pragma unroll
        for (int j = 0; j < 4; j++)
#pragma unroll
            for (int q = 0; q < 4; q++) C[i][j][q] = 0.f;

    const int a_row_off = ((lane >> 3) & 1) * 8 + (lane & 7);
    const int a_k_off   = ((lane >> 4) & 1) * 8;
    const int b_row_off = ((lane >> 4) & 1) * 8 + (lane & 7);
    const int b_k_off   = ((lane >> 3) & 1) * 8;

    float4 Ar[4];   // MODE 0 register-prefetch

    auto issue_stage = [&](int kt, int buf) {
        const int k0 = kt * 32;
        uint32_t bhB = sbase + (uint32_t)(buf * PLANES + P_BH) * 10240u;
#pragma unroll
        for (int i = 0; i < 2; i++) {
            int f = tid + i * 256;
            int row = f >> 2, m = f & 3;
            size_t go = (size_t)(n0 + row) * KB + k0 + m * 8;
            uint32_t so = (uint32_t)(row * 40 + m * 8) * 2;
            cp16(bhB + so, WH + go, 16);
            if (MODE == 1) {
                uint32_t blB = sbase + (uint32_t)(buf * PLANES + P_BL) * 10240u;
                cp16(blB + so, g_WcL + go, 16);
            }
        }
        if (MODE == 1) {
            uint32_t ahB = sbase + (uint32_t)(buf * PLANES + P_AH) * 10240u;
#pragma unroll
            for (int i = 0; i < 2; i++) {
                int f = tid + i * 256;
                int row = f >> 2, m = f & 3;
                bool v = (m0 + row) < NE;
                size_t rr = v ? (size_t)(m0 + row) : 0;
                size_t go = rr * KB1 + k0 + m * 8;
                uint32_t so = (uint32_t)(row * 40 + m * 8) * 2;
                cp16(ahB + so, g_AH + go, v ? 16 : 0);
            }
        }
        CP_COMMIT();
    };

    auto loadA = [&](int kt) {   // MODE 0 only
        const int k0 = kt * 32;
#pragma unroll
        for (int i = 0; i < 4; i++) {
            int f = tid + i * 256;
            int row = f >> 3, c4 = (f & 7) << 2;
            int gr = m0 + row;
            Ar[i] = (gr < NE) ? *(const float4*)(A_ext + (size_t)gr * KD + k0 + c4)
                              : make_float4(0.f, 0.f, 0.f, 0.f);
        }
    };

    auto storeA = [&](int buf) {  // MODE 0 only: hi-plane only
        __half* Ah = dsm + (size_t)(buf * PLANES + P_AH) * 5120;
#pragma unroll
        for (int i = 0; i < 4; i++) {
            int f = tid + i * 256;
            int row = f >> 3, c4 = (f & 7) << 2;
            float4 v = Ar[i];
            __half2 hp0; hp0.x = __float2half_rn(v.x); hp0.y = __float2half_rn(v.y);
            __half2 hp1; hp1.x = __float2half_rn(v.z); hp1.y = __float2half_rn(v.w);
            *(__half2*)(Ah + row * 40 + c4)     = hp0;
            *(__half2*)(Ah + row * 40 + c4 + 2) = hp1;
        }
    };

    // ---- prologue
    if (MODE == 0) loadA(0);
    issue_stage(0, 0);

    // ---- mainloop
    for (int kt = 0; kt < NK; kt++) {
        const int cur = kt & 1;
        if (MODE == 0) storeA(cur);
        CP_WAIT0();
        __syncthreads();
        if (kt + 1 < NK) {
            issue_stage(kt + 1, cur ^ 1);
            if (MODE == 0) loadA(kt + 1);
        }

        const uint32_t sAh = sbase + (uint32_t)(cur * PLANES + P_AH) * 10240u;
        const uint32_t sBh = sbase + (uint32_t)(cur * PLANES + P_BH) * 10240u;
        const uint32_t sBl = sbase + (uint32_t)(cur * PLANES + P_BL) * 10240u;

#pragma unroll
        for (int kh = 0; kh < 2; kh++) {
            uint32_t Af_h[4][4];
#pragma unroll
            for (int mf = 0; mf < 4; mf++) {
                int row = wm * 64 + mf * 16 + a_row_off;
                uint32_t off = (uint32_t)(row * 40 + kh * 16 + a_k_off) * 2;
                ldsm4(sAh + off, Af_h[mf][0], Af_h[mf][1], Af_h[mf][2], Af_h[mf][3]);
            }
            uint32_t Bf_h[2][4];
            uint32_t Bf_l[2][4];
#pragma unroll
            for (int nf = 0; nf < 2; nf++) {
                int row = wn * 32 + nf * 16 + b_row_off;
                uint32_t off = (uint32_t)(row * 40 + kh * 16 + b_k_off) * 2;
                ldsm4(sBh + off, Bf_h[nf][0], Bf_h[nf][1], Bf_h[nf][2], Bf_h[nf][3]);
                if (MODE == 1)
                    ldsm4(sBl + off, Bf_l[nf][0], Bf_l[nf][1], Bf_l[nf][2], Bf_l[nf][3]);
            }
#pragma unroll
            for (int mf = 0; mf < 4; mf++) {
#pragma unroll
                for (int j = 0; j < 4; j++) {
                    int nf = j >> 1;
                    int hh = j & 1;
                    mma16816(C[mf][j], Af_h[mf], Bf_h[nf][hh * 2], Bf_h[nf][hh * 2 + 1]);
                    if (MODE == 1)
                        mma16816(C[mf][j], Af_h[mf], Bf_l[nf][hh * 2], Bf_l[nf][hh * 2 + 1]);
                }
            }
        }
    }

    // ---- epilogue
    float alpha = 0.f;
    if (MODE == 1) alpha = 1.f / (1.f + expf(-gate[0]));
    const int g = lane >> 2, t = lane & 3;

#pragma unroll
    for (int mf = 0; mf < 4; mf++) {
        int r0 = m0 + wm * 64 + mf * 16 + g;
#pragma unroll
        for (int j = 0; j < 4; j++) {
            int col = n0 + wn * 32 + j * 8 + t * 2;
            float b0 = bias[col], b1 = bias[col + 1];
#pragma unroll
            for (int half = 0; half < 2; half++) {
                int row = r0 + half * 8;
                if (row >= NE) continue;
                float v0 = C[mf][j][half * 2 + 0] + b0;
                float v1 = C[mf][j][half * 2 + 1] + b1;
                if (MODE == 0) {
                    __half h0 = __float2half_rn(v0);
                    __half h1 = __float2half_rn(v1);
                    __half2 hp; hp.x = h0; hp.y = h1;
                    __half2 lp;
                    lp.x = __float2half_rn(v0 - __half2float(h0));
                    lp.y = __float2half_rn(v1 - __half2float(h1));
                    *(__half2*)&g_AH[(size_t)row * KB1 + col] = hp;
                    *(__half2*)&g_AL[(size_t)row * KB1 + col] = lp;
                } else {
                    __half2 rh = *(const __half2*)&g_AH[(size_t)row * KB1 + col];
                    __half2 rl = *(const __half2*)&g_AL[(size_t)row * KB1 + col];
                    float rr0 = __half2float(rh.x) + __half2float(rl.x);
                    float rr1 = __half2float(rh.y) + __half2float(rl.y);
                    float u;
                    u = 0.5f * v0; u = u > 0.f ? u : 0.2f * u;
                    float o0 = alpha * u + (1.f - alpha) * rr0;
                    u = 0.5f * v1; u = u > 0.f ? u : 0.2f * u;
                    float o1 = alpha * u + (1.f - alpha) * rr1;
                    *(float2*)&g_he[(size_t)row * HD + col] = make_float2(o0, o1);
                }
            }
        }
    }
}

// ---------------- KAN classifier: SiLU base + closed-form cubic B-spline ----
__global__ __launch_bounds__(256) void kan_kernel(const float* __restrict__ base_w,
                                                  const float* __restrict__ spline_w,
                                                  float* __restrict__ out) {
    __shared__ float sbw[2 * 256];
    __shared__ float ssw[8 * 2 * 256];   // [g][o][h]
    int tid = threadIdx.x;
    for (int i = tid; i < 512; i += 256) sbw[i] = base_w[i];
    for (int i = tid; i < 4096; i += 256) {
        int o = i >> 11;
        int h = (i >> 3) & 255;
        int g = i & 7;
        ssw[g * 512 + o * 256 + h] = spline_w[i];
    }
    __syncthreads();

    const float c6 = 1.f / 6.f;
    int warp = tid >> 5, lane = tid & 31;
    int base = blockIdx.x * 64;
    for (int nn = warp; nn < 64; nn += 8) {
        int n = base + nn;
        if (n >= NE) break;
        float acc0 = 0.f, acc1 = 0.f;
#pragma unroll
        for (int it = 0; it < 8; it++) {
            int h = it * 32 + lane;
            float x = g_he[(size_t)n * HD + h];
            float sil = x * __fdividef(1.f, 1.f + __expf(-x));
            acc0 += sil * sbw[h];
            acc1 += sil * sbw[256 + h];
            float tt = (x + 2.2f) * 2.5f;
            float fj = floorf(tt);
            int j = (int)fj;
            if (j >= 0 && j < 11) {
                float u = tt - fj;
                float u2 = u * u, u3 = u2 * u;
                float p0 = u3 * c6;
                float p1 = (1.f + 3.f * (u + u2) - 3.f * u3) * c6;
                float p2 = (4.f - 6.f * u2 + 3.f * u3) * c6;
                float om = 1.f - u;
                float p3 = om * om * om * c6;
                if (j < 8) {
                    acc0 += p0 * ssw[j * 512 + h];
                    acc1 += p0 * ssw[j * 512 + 256 + h];
                }
                int g1 = j - 1;
                if (g1 >= 0 && g1 < 8) {
                    acc0 += p1 * ssw[g1 * 512 + h];
                    acc1 += p1 * ssw[g1 * 512 + 256 + h];
                }
                int g2 = j - 2;
                if (g2 >= 0 && g2 < 8) {
                    acc0 += p2 * ssw[g2 * 512 + h];
                    acc1 += p2 * ssw[g2 * 512 + 256 + h];
                }
                int g3 = j - 3;
                if (g3 >= 0) {
                    acc0 += p3 * ssw[g3 * 512 + h];
                    acc1 += p3 * ssw[g3 * 512 + 256 + h];
                }
            }
        }
#pragma unroll
        for (int off = 16; off; off >>= 1) {
            acc0 += __shfl_xor_sync(0xffffffff, acc0, off);
            acc1 += __shfl_xor_sync(0xffffffff, acc1, off);
        }
        if (lane == 0) {
            out[n * 2 + 0] = acc0;
            out[n * 2 + 1] = acc1;
        }
    }
}

// ---------------- launch ----------------------------------------------------
extern "C" void kernel_launch(void* const* d_in, const int* in_sizes, int n_in,
                              void* d_out, int out_size) {
    const float* x_email   = (const float*)d_in[0];
    const float* x_url     = (const float*)d_in[1];
    const float* x_sender  = (const float*)d_in[2];
    const float* W_e       = (const float*)d_in[3];
    const float* b_e       = (const float*)d_in[4];
    const float* W_u       = (const float*)d_in[5];
    const float* b_u       = (const float*)d_in[6];
    const float* W_s       = (const float*)d_in[7];
    const float* b_s       = (const float*)d_in[8];
    const float* Wl_ue     = (const float*)d_in[12];
    const float* bl_ue     = (const float*)d_in[13];
    const float* Wr_ue     = (const float*)d_in[14];
    const float* Wl_se     = (const float*)d_in[15];
    const float* bl_se     = (const float*)d_in[16];
    const float* Wr_se     = (const float*)d_in[17];
    const float* gate      = (const float*)d_in[21];
    const float* kan_base  = (const float*)d_in[22];
    const float* kan_spline= (const float*)d_in[23];
    const int*   ue_src    = (const int*)d_in[26];
    const int*   ue_dst    = (const int*)d_in[27];
    const int*   se_src    = (const int*)d_in[28];
    const int*   se_dst    = (const int*)d_in[29];
    int n_ue = in_sizes[26];
    int n_se = in_sizes[28];
    float* out = (float*)d_out;

    cudaFuncSetAttribute((void*)gemm_tc<0>, cudaFuncAttributeMaxDynamicSharedMemorySize, 81920);
    cudaFuncSetAttribute((void*)gemm_tc<1>, cudaFuncAttributeMaxDynamicSharedMemorySize, 81920);

    dim3 ggrid((NE + 127) / 128, 2);

    zero_kernel<<<512, 256>>>();
    prep_kernel<<<KD, 256>>>(W_e, Wr_ue, Wr_se, bl_ue, bl_se);
    prep2_kernel<<<HD, 32>>>(Wl_ue, W_u, b_u, Wl_se, W_s, b_s);
    agg_ue_kernel<<<(n_ue + 255) / 256, 256>>>(ue_src, ue_dst, x_url, n_ue);
    agg_se_kernel<<<(n_se + 255) / 256, 256>>>(se_src, se_dst, x_sender, n_se);
    gemm_tc<0><<<ggrid, 256, 40960>>>(x_email, b_e, nullptr);
    qprep_kernel<<<(NE + 255) / 256, 256>>>();
    gemm_tc<1><<<ggrid, 256, 61440>>>(nullptr, nullptr, gate);
    kan_kernel<<<(NE + 63) / 64, 256>>>(kan_base, kan_spline, out);
}

// round 9
// speedup vs baseline: 5.0043x; 1.2350x over previous
#include <cuda_runtime.h>
#include <cuda_fp16.h>
#include <stdint.h>
#include <math.h>

#define NE 50000
#define HD 256
#define KD 768
#define KB1 288   // phase-2 K: 256 he + 32 q (11 real + pad)

// SMEM layout (halves)
#define A2_STRIDE 296                            // 592 B row stride: 592 mod 128 = 80 -> conflict-free ldsm
#define A2_HALVES (128 * A2_STRIDE)              // 37888
#define S0 A2_HALVES                             // staging region base
#define P1_STAGE 15360                           // phase-1 stage: Ah(5120) + Bh(10240)
#define P2_STAGE 20480                           // phase-2 stage: Bh(10240) + Bl(10240)
#define SMEM_HALVES (A2_HALVES + 2 * P2_STAGE)   // 78848
#define SMEM_BYTES (SMEM_HALVES * 2)             // 157696

// ---------------- scratch ----------------------------------------------------
__device__ float g_he[(size_t)NE * HD];    // final he (fp32, feeds KAN)
__device__ __half g_WeH[HD * KD];          // W_e fp16 [n][k] k<768
__device__ __half g_WcH[HD * KB1];         // W' hi [n][k] k<288
__device__ __half g_WcL[HD * KB1];         // W' lo
__device__ float g_bias2[HD];              // bl_ue + bl_se
__device__ float g_sum8[NE * 8];
__device__ float g_sum1[NE];
__device__ int   g_cnt_ue[NE];
__device__ int   g_cnt_se[NE];

// ---------------- zero accumulators (re-zeroed every graph replay) ----------
__global__ void zero_kernel() {
    int i = blockIdx.x * blockDim.x + threadIdx.x;
    int stride = gridDim.x * blockDim.x;
    for (int j = i; j < NE * 8; j += stride) g_sum8[j] = 0.f;
    for (int j = i; j < NE; j += stride) { g_sum1[j] = 0.f; g_cnt_ue[j] = 0; g_cnt_se[j] = 0; }
}

// ---------------- weight prep ------------------------------------------------
__global__ void prep_kernel(const float* __restrict__ W_e,
                            const float* __restrict__ Wr_ue, const float* __restrict__ Wr_se,
                            const float* __restrict__ bl_ue, const float* __restrict__ bl_se) {
    int idx = blockIdx.x * 256 + threadIdx.x;   // covers 256*768
    if (idx < HD) g_bias2[idx] = bl_ue[idx] + bl_se[idx];
    g_WeH[idx] = __float2half_rn(W_e[idx]);
    if (idx < HD * HD) {
        int n = idx >> 8, k = idx & 255;
        float w = Wr_ue[idx] + Wr_se[idx];
        __half wh = __float2half_rn(w);
        g_WcH[n * KB1 + k] = wh;
        g_WcL[n * KB1 + k] = __float2half_rn(w - __half2float(wh));
    }
}

// ---------------- prep2: rank-11 correction columns of W' -------------------
__global__ void prep2_kernel(const float* __restrict__ Wl_ue, const float* __restrict__ W_u,
                             const float* __restrict__ b_u,
                             const float* __restrict__ Wl_se, const float* __restrict__ W_s,
                             const float* __restrict__ b_s) {
    int n = blockIdx.x;
    int c = threadIdx.x;    // 0..31
    float acc = 0.f;
    if (c < 8) {
        for (int h = 0; h < HD; h++) acc += Wl_ue[n * HD + h] * W_u[h * 8 + c];
    } else if (c == 8) {
        for (int h = 0; h < HD; h++) acc += Wl_ue[n * HD + h] * b_u[h];
    } else if (c == 9) {
        for (int h = 0; h < HD; h++) acc += Wl_se[n * HD + h] * W_s[h];
    } else if (c == 10) {
        for (int h = 0; h < HD; h++) acc += Wl_se[n * HD + h] * b_s[h];
    }
    __half h = __float2half_rn(acc);
    g_WcH[n * KB1 + 256 + c] = h;
    g_WcL[n * KB1 + 256 + c] = __float2half_rn(acc - __half2float(h));
}

// ---------------- edge aggregation ------------------------------------------
__global__ void agg_ue_kernel(const int* __restrict__ src, const int* __restrict__ dst,
                              const float* __restrict__ x_url, int nE) {
    int e = blockIdx.x * blockDim.x + threadIdx.x;
    if (e >= nE) return;
    int s = src[e], d = dst[e];
    const float4* xu = (const float4*)(x_url + (size_t)s * 8);
    float4 a = xu[0], b = xu[1];
    float* p = g_sum8 + (size_t)d * 8;
    asm volatile("red.global.add.v4.f32 [%0], {%1,%2,%3,%4};"
                 :: "l"(p), "f"(a.x), "f"(a.y), "f"(a.z), "f"(a.w) : "memory");
    asm volatile("red.global.add.v4.f32 [%0], {%1,%2,%3,%4};"
                 :: "l"(p + 4), "f"(b.x), "f"(b.y), "f"(b.z), "f"(b.w) : "memory");
    asm volatile("red.global.add.s32 [%0], %1;" :: "l"(g_cnt_ue + d), "r"(1) : "memory");
}

__global__ void agg_se_kernel(const int* __restrict__ src, const int* __restrict__ dst,
                              const float* __restrict__ x_sender, int nE) {
    int e = blockIdx.x * blockDim.x + threadIdx.x;
    if (e >= nE) return;
    int d = dst[e];
    float v = x_sender[src[e]];
    asm volatile("red.global.add.f32 [%0], %1;" :: "l"(g_sum1 + d), "f"(v) : "memory");
    asm volatile("red.global.add.s32 [%0], %1;" :: "l"(g_cnt_se + d), "r"(1) : "memory");
}

// ---------------- cp.async helpers ------------------------------------------
__device__ __forceinline__ void cp16(uint32_t d, const void* s, int sz) {
    asm volatile("cp.async.cg.shared.global [%0], [%1], 16, %2;"
                 :: "r"(d), "l"(s), "r"(sz));
}
#define CP_COMMIT() asm volatile("cp.async.commit_group;")
#define CP_WAIT0()  asm volatile("cp.async.wait_group 0;")

__device__ __forceinline__ void ldsm4(uint32_t addr, uint32_t& r0, uint32_t& r1,
                                      uint32_t& r2, uint32_t& r3) {
    asm volatile("ldmatrix.sync.aligned.m8n8.x4.shared.b16 {%0,%1,%2,%3}, [%4];"
                 : "=r"(r0), "=r"(r1), "=r"(r2), "=r"(r3) : "r"(addr));
}

__device__ __forceinline__ void mma16816(float* c, const uint32_t* a, uint32_t b0, uint32_t b1) {
    asm volatile("mma.sync.aligned.m16n8k16.row.col.f32.f16.f16.f32 "
                 "{%0,%1,%2,%3}, {%4,%5,%6,%7}, {%8,%9}, {%0,%1,%2,%3};"
                 : "+f"(c[0]), "+f"(c[1]), "+f"(c[2]), "+f"(c[3])
                 : "r"(a[0]), "r"(a[1]), "r"(a[2]), "r"(a[3]), "r"(b0), "r"(b1));
}

// ---------------- fused GEMM: projection + conv + activation ----------------
// Phase 1: he_pre[128x256] = x_email_tile @ W_e^T + b_e -> fp16 A2 in SMEM
//          (+ rank-11 q vector from edge aggregates into A2 cols 256..287)
// Phase 2: out = A2[128x288] @ W'^T + bias2 (2 MMAs: hi+lo weights)
//          epilogue: 0.5x, leaky(0.2), gated residual (A2 hi) -> g_he fp32
__global__ __launch_bounds__(512) void fused_gemm(const float* __restrict__ x_email,
                                                  const float* __restrict__ b_e,
                                                  const float* __restrict__ gate) {
    extern __shared__ __half dsm[];
    const uint32_t sbase = (uint32_t)__cvta_generic_to_shared(dsm);
    __half* A2 = dsm;

    const int tid = threadIdx.x;
    const int lane = tid & 31;
    const int warp = tid >> 5;      // 0..15
    const int wm = warp & 1;        // 2 m-slabs of 64
    const int wn = warp >> 1;       // 8 n-slabs of 32
    const int m0 = blockIdx.x * 128;

    const int a_row_off = ((lane >> 3) & 1) * 8 + (lane & 7);
    const int a_k_off   = ((lane >> 4) & 1) * 8;
    const int b_row_off = ((lane >> 4) & 1) * 8 + (lane & 7);
    const int b_k_off   = ((lane >> 3) & 1) * 8;
    const int g = lane >> 2, t = lane & 3;

    float C[4][4][4];
#pragma unroll
    for (int i = 0; i < 4; i++)
#pragma unroll
        for (int j = 0; j < 4; j++)
#pragma unroll
            for (int q = 0; q < 4; q++) C[i][j][q] = 0.f;

    float4 Ar[2];

    // ================= PHASE 1: K = 768 =================
    auto issueB1 = [&](int kt, int buf) {
        const int k0 = kt * 32;
        uint32_t bh = sbase + (uint32_t)(S0 + buf * P1_STAGE + 5120) * 2u;
#pragma unroll
        for (int i = 0; i < 2; i++) {
            int f = tid + i * 512;          // 0..1023 -> 256 rows x 4 chunks
            int row = f >> 2, m = f & 3;
            cp16(bh + (uint32_t)(row * 40 + m * 8) * 2,
                 g_WeH + (size_t)row * KD + k0 + m * 8, 16);
        }
        CP_COMMIT();
    };
    auto loadA1 = [&](int kt) {
        const int k0 = kt * 32;
#pragma unroll
        for (int i = 0; i < 2; i++) {
            int f = tid + i * 512;          // 0..1023 -> 128 rows x 8 float4
            int row = f >> 3, c4 = (f & 7) << 2;
            int gr = m0 + row;
            Ar[i] = (gr < NE) ? *(const float4*)(x_email + (size_t)gr * KD + k0 + c4)
                              : make_float4(0.f, 0.f, 0.f, 0.f);
        }
    };
    auto storeA1 = [&](int buf) {
        __half* Ah = dsm + S0 + buf * P1_STAGE;
#pragma unroll
        for (int i = 0; i < 2; i++) {
            int f = tid + i * 512;
            int row = f >> 3, c4 = (f & 7) << 2;
            float4 v = Ar[i];
            __half2 hp0; hp0.x = __float2half_rn(v.x); hp0.y = __float2half_rn(v.y);
            __half2 hp1; hp1.x = __float2half_rn(v.z); hp1.y = __float2half_rn(v.w);
            *(__half2*)(Ah + row * 40 + c4)     = hp0;
            *(__half2*)(Ah + row * 40 + c4 + 2) = hp1;
        }
    };

    loadA1(0);
    issueB1(0, 0);

    for (int kt = 0; kt < 24; kt++) {
        const int cur = kt & 1;
        storeA1(cur);
        CP_WAIT0();
        __syncthreads();
        if (kt + 1 < 24) {
            issueB1(kt + 1, cur ^ 1);
            loadA1(kt + 1);
        }
        const uint32_t sAh = sbase + (uint32_t)(S0 + cur * P1_STAGE) * 2u;
        const uint32_t sBh = sbase + (uint32_t)(S0 + cur * P1_STAGE + 5120) * 2u;
#pragma unroll
        for (int kh = 0; kh < 2; kh++) {
            uint32_t Af[4][4];
#pragma unroll
            for (int mf = 0; mf < 4; mf++) {
                int row = wm * 64 + mf * 16 + a_row_off;
                uint32_t off = (uint32_t)(row * 40 + kh * 16 + a_k_off) * 2;
                ldsm4(sAh + off, Af[mf][0], Af[mf][1], Af[mf][2], Af[mf][3]);
            }
            uint32_t Bf[2][4];
#pragma unroll
            for (int nf = 0; nf < 2; nf++) {
                int row = wn * 32 + nf * 16 + b_row_off;
                uint32_t off = (uint32_t)(row * 40 + kh * 16 + b_k_off) * 2;
                ldsm4(sBh + off, Bf[nf][0], Bf[nf][1], Bf[nf][2], Bf[nf][3]);
            }
#pragma unroll
            for (int mf = 0; mf < 4; mf++) {
#pragma unroll
                for (int j = 0; j < 4; j++) {
                    int nf = j >> 1;
                    int hh = j & 1;
                    mma16816(C[mf][j], Af[mf], Bf[nf][hh * 2], Bf[nf][hh * 2 + 1]);
                }
            }
        }
    }

    // ---- epilogue 1: he_pre + b_e -> fp16 A2 cols 0..255
#pragma unroll
    for (int mf = 0; mf < 4; mf++) {
        int rl0 = wm * 64 + mf * 16 + g;
#pragma unroll
        for (int j = 0; j < 4; j++) {
            int col = wn * 32 + j * 8 + t * 2;
            float b0 = b_e[col], b1 = b_e[col + 1];
#pragma unroll
            for (int half = 0; half < 2; half++) {
                int rl = rl0 + half * 8;
                __half2 hp;
                hp.x = __float2half_rn(C[mf][j][half * 2 + 0] + b0);
                hp.y = __float2half_rn(C[mf][j][half * 2 + 1] + b1);
                *(__half2*)&A2[rl * A2_STRIDE + col] = hp;
            }
        }
    }

    // ---- q vector: A2 cols 256..287 (4 threads per row, 8 cols each)
    {
        int rl = tid >> 2;
        int cc = (tid & 3) * 8;
        int gr = m0 + rl;
        float qv[8];
#pragma unroll
        for (int i = 0; i < 8; i++) qv[i] = 0.f;
        if (gr < NE) {
            if (cc == 0) {
                int cu = g_cnt_ue[gr];
                if (cu > 0) {
                    float inv = 1.f / (float)cu;
#pragma unroll
                    for (int c = 0; c < 8; c++) qv[c] = g_sum8[(size_t)gr * 8 + c] * inv;
                }
            } else if (cc == 8) {
                if (g_cnt_ue[gr] > 0) qv[0] = 1.f;      // k=264 flag_u
                int cs = g_cnt_se[gr];
                if (cs > 0) {
                    qv[1] = g_sum1[gr] / (float)cs;     // k=265 mean_s
                    qv[2] = 1.f;                        // k=266 flag_s
                }
            }
        }
#pragma unroll
        for (int i = 0; i < 8; i += 2) {
            __half2 hp;
            hp.x = __float2half_rn(qv[i]);
            hp.y = __float2half_rn(qv[i + 1]);
            *(__half2*)&A2[rl * A2_STRIDE + 256 + cc + i] = hp;
        }
    }
    __syncthreads();

    // ================= PHASE 2: K = 288 =================
#pragma unroll
    for (int i = 0; i < 4; i++)
#pragma unroll
        for (int j = 0; j < 4; j++)
#pragma unroll
            for (int q = 0; q < 4; q++) C[i][j][q] = 0.f;

    auto issueB2 = [&](int kt, int buf) {
        const int k0 = kt * 32;
        uint32_t bh = sbase + (uint32_t)(S0 + buf * P2_STAGE) * 2u;
        uint32_t bl = bh + 10240u * 2u;
#pragma unroll
        for (int i = 0; i < 2; i++) {
            int f = tid + i * 512;
            int row = f >> 2, m = f & 3;
            uint32_t so = (uint32_t)(row * 40 + m * 8) * 2;
            size_t go = (size_t)row * KB1 + k0 + m * 8;
            cp16(bh + so, g_WcH + go, 16);
            cp16(bl + so, g_WcL + go, 16);
        }
        CP_COMMIT();
    };

    issueB2(0, 0);

    for (int kt = 0; kt < 9; kt++) {
        const int cur = kt & 1;
        CP_WAIT0();
        __syncthreads();
        if (kt + 1 < 9) issueB2(kt + 1, cur ^ 1);

        const uint32_t sBh = sbase + (uint32_t)(S0 + cur * P2_STAGE) * 2u;
        const uint32_t sBl = sBh + 10240u * 2u;
#pragma unroll
        for (int kh = 0; kh < 2; kh++) {
            uint32_t Af[4][4];
#pragma unroll
            for (int mf = 0; mf < 4; mf++) {
                int row = wm * 64 + mf * 16 + a_row_off;
                uint32_t off = (uint32_t)(row * A2_STRIDE + kt * 32 + kh * 16 + a_k_off) * 2;
                ldsm4(sbase + off, Af[mf][0], Af[mf][1], Af[mf][2], Af[mf][3]);
            }
            uint32_t Bfh[2][4], Bfl[2][4];
#pragma unroll
            for (int nf = 0; nf < 2; nf++) {
                int row = wn * 32 + nf * 16 + b_row_off;
                uint32_t off = (uint32_t)(row * 40 + kh * 16 + b_k_off) * 2;
                ldsm4(sBh + off, Bfh[nf][0], Bfh[nf][1], Bfh[nf][2], Bfh[nf][3]);
                ldsm4(sBl + off, Bfl[nf][0], Bfl[nf][1], Bfl[nf][2], Bfl[nf][3]);
            }
#pragma unroll
            for (int mf = 0; mf < 4; mf++) {
#pragma unroll
                for (int j = 0; j < 4; j++) {
                    int nf = j >> 1;
                    int hh = j & 1;
                    mma16816(C[mf][j], Af[mf], Bfh[nf][hh * 2], Bfh[nf][hh * 2 + 1]);
                    mma16816(C[mf][j], Af[mf], Bfl[nf][hh * 2], Bfl[nf][hh * 2 + 1]);
                }
            }
        }
    }

    // ---- epilogue 2: bias2, 0.5x, leaky, gated residual -> g_he
    const float alpha = 1.f / (1.f + expf(-gate[0]));
#pragma unroll
    for (int mf = 0; mf < 4; mf++) {
        int rl0 = wm * 64 + mf * 16 + g;
#pragma unroll
        for (int j = 0; j < 4; j++) {
            int col = wn * 32 + j * 8 + t * 2;
            float b0 = g_bias2[col], b1 = g_bias2[col + 1];
#pragma unroll
            for (int half = 0; half < 2; half++) {
                int rl = rl0 + half * 8;
                int row = m0 + rl;
                if (row >= NE) continue;
                float v0 = C[mf][j][half * 2 + 0] + b0;
                float v1 = C[mf][j][half * 2 + 1] + b1;
                __half2 rh = *(const __half2*)&A2[rl * A2_STRIDE + col];
                float rr0 = __half2float(rh.x);
                float rr1 = __half2float(rh.y);
                float u;
                u = 0.5f * v0; u = u > 0.f ? u : 0.2f * u;
                float o0 = alpha * u + (1.f - alpha) * rr0;
                u = 0.5f * v1; u = u > 0.f ? u : 0.2f * u;
                float o1 = alpha * u + (1.f - alpha) * rr1;
                *(float2*)&g_he[(size_t)row * HD + col] = make_float2(o0, o1);
            }
        }
    }
}

// ---------------- KAN classifier: SiLU base + closed-form cubic B-spline ----
__global__ __launch_bounds__(256) void kan_kernel(const float* __restrict__ base_w,
                                                  const float* __restrict__ spline_w,
                                                  float* __restrict__ out) {
    __shared__ float sbw[2 * 256];
    __shared__ float ssw[8 * 2 * 256];   // [g][o][h]
    int tid = threadIdx.x;
    for (int i = tid; i < 512; i += 256) sbw[i] = base_w[i];
    for (int i = tid; i < 4096; i += 256) {
        int o = i >> 11;
        int h = (i >> 3) & 255;
        int g = i & 7;
        ssw[g * 512 + o * 256 + h] = spline_w[i];
    }
    __syncthreads();

    const float c6 = 1.f / 6.f;
    int warp = tid >> 5, lane = tid & 31;
    int base = blockIdx.x * 64;
    for (int nn = warp; nn < 64; nn += 8) {
        int n = base + nn;
        if (n >= NE) break;
        float acc0 = 0.f, acc1 = 0.f;
#pragma unroll
        for (int it = 0; it < 8; it++) {
            int h = it * 32 + lane;
            float x = g_he[(size_t)n * HD + h];
            float sil = x * __fdividef(1.f, 1.f + __expf(-x));
            acc0 += sil * sbw[h];
            acc1 += sil * sbw[256 + h];
            float tt = (x + 2.2f) * 2.5f;
            float fj = floorf(tt);
            int j = (int)fj;
            if (j >= 0 && j < 11) {
                float u = tt - fj;
                float u2 = u * u, u3 = u2 * u;
                float p0 = u3 * c6;
                float p1 = (1.f + 3.f * (u + u2) - 3.f * u3) * c6;
                float p2 = (4.f - 6.f * u2 + 3.f * u3) * c6;
                float om = 1.f - u;
                float p3 = om * om * om * c6;
                if (j < 8) {
                    acc0 += p0 * ssw[j * 512 + h];
                    acc1 += p0 * ssw[j * 512 + 256 + h];
                }
                int g1 = j - 1;
                if (g1 >= 0 && g1 < 8) {
                    acc0 += p1 * ssw[g1 * 512 + h];
                    acc1 += p1 * ssw[g1 * 512 + 256 + h];
                }
                int g2 = j - 2;
                if (g2 >= 0 && g2 < 8) {
                    acc0 += p2 * ssw[g2 * 512 + h];
                    acc1 += p2 * ssw[g2 * 512 + 256 + h];
                }
                int g3 = j - 3;
                if (g3 >= 0) {
                    acc0 += p3 * ssw[g3 * 512 + h];
                    acc1 += p3 * ssw[g3 * 512 + 256 + h];
                }
            }
        }
#pragma unroll
        for (int off = 16; off; off >>= 1) {
            acc0 += __shfl_xor_sync(0xffffffff, acc0, off);
            acc1 += __shfl_xor_sync(0xffffffff, acc1, off);
        }
        if (lane == 0) {
            out[n * 2 + 0] = acc0;
            out[n * 2 + 1] = acc1;
        }
    }
}

// ---------------- launch ----------------------------------------------------
extern "C" void kernel_launch(void* const* d_in, const int* in_sizes, int n_in,
                              void* d_out, int out_size) {
    const float* x_email   = (const float*)d_in[0];
    const float* x_url     = (const float*)d_in[1];
    const float* x_sender  = (const float*)d_in[2];
    const float* W_e       = (const float*)d_in[3];
    const float* b_e       = (const float*)d_in[4];
    const float* W_u       = (const float*)d_in[5];
    const float* b_u       = (const float*)d_in[6];
    const float* W_s       = (const float*)d_in[7];
    const float* b_s       = (const float*)d_in[8];
    const float* Wl_ue     = (const float*)d_in[12];
    const float* bl_ue     = (const float*)d_in[13];
    const float* Wr_ue     = (const float*)d_in[14];
    const float* Wl_se     = (const float*)d_in[15];
    const float* bl_se     = (const float*)d_in[16];
    const float* Wr_se     = (const float*)d_in[17];
    const float* gate      = (const float*)d_in[21];
    const float* kan_base  = (const float*)d_in[22];
    const float* kan_spline= (const float*)d_in[23];
    const int*   ue_src    = (const int*)d_in[26];
    const int*   ue_dst    = (const int*)d_in[27];
    const int*   se_src    = (const int*)d_in[28];
    const int*   se_dst    = (const int*)d_in[29];
    int n_ue = in_sizes[26];
    int n_se = in_sizes[28];
    float* out = (float*)d_out;

    cudaFuncSetAttribute((void*)fused_gemm, cudaFuncAttributeMaxDynamicSharedMemorySize,
                         SMEM_BYTES);

    zero_kernel<<<512, 256>>>();
    prep_kernel<<<KD, 256>>>(W_e, Wr_ue, Wr_se, bl_ue, bl_se);
    prep2_kernel<<<HD, 32>>>(Wl_ue, W_u, b_u, Wl_se, W_s, b_s);
    agg_ue_kernel<<<(n_ue + 255) / 256, 256>>>(ue_src, ue_dst, x_url, n_ue);
    agg_se_kernel<<<(n_se + 255) / 256, 256>>>(se_src, se_dst, x_sender, n_se);
    fused_gemm<<<(NE + 127) / 128, 512, SMEM_BYTES>>>(x_email, b_e, gate);
    kan_kernel<<<(NE + 63) / 64, 256>>>(kan_base, kan_spline, out);
}

// round 10
// speedup vs baseline: 5.6540x; 1.1298x over previous
#include <cuda_runtime.h>
#include <cuda_fp16.h>
#include <stdint.h>
#include <math.h>

#define NE 50000
#define HD 256
#define KD 768
#define KB1 288   // phase-2 K: 256 he + 32 q (11 real + pad)

// SMEM layout (halves)
#define A2_STRIDE 296                            // 592 B row stride: conflict-free ldsm
#define A2_HALVES (128 * A2_STRIDE)              // 37888
#define S0 A2_HALVES                             // staging region base (halves)
#define P1_STAGE 15360                           // phase-1 stage: Ah(5120) + Bh(10240)
#define P2_STAGE 20480                           // phase-2 stage: Bh(10240) + Bl(10240)
#define KAN_OFF (A2_HALVES + 2 * P2_STAGE)       // 78848 halves = 157696 B
#define KAN_FLOATS 4608                          // sbw 512 + ssw 4096
#define SMEM_BYTES (KAN_OFF * 2 + KAN_FLOATS * 4)  // 176128

// ---------------- scratch ----------------------------------------------------
__device__ __half g_WeH[HD * KD];          // W_e fp16 [n][k] k<768
__device__ __half g_WcH[HD * KB1];         // W' hi [n][k] k<288
__device__ __half g_WcL[HD * KB1];         // W' lo
__device__ float g_bias2[HD];              // bl_ue + bl_se
__device__ float g_sum8[NE * 8];
__device__ float g_sum1[NE];
__device__ int   g_cnt_ue[NE];
__device__ int   g_cnt_se[NE];

// ---------------- weight prep (+ accumulator zeroing, fused) ----------------
__global__ void prep_kernel(const float* __restrict__ W_e,
                            const float* __restrict__ Wr_ue, const float* __restrict__ Wr_se,
                            const float* __restrict__ bl_ue, const float* __restrict__ bl_se) {
    int idx = blockIdx.x * 256 + threadIdx.x;   // 196608 threads, covers 256*768
    // zero edge accumulators (re-zeroed every graph replay)
    for (int j = idx; j < NE * 8; j += 196608) g_sum8[j] = 0.f;
    if (idx < NE) { g_sum1[idx] = 0.f; g_cnt_ue[idx] = 0; g_cnt_se[idx] = 0; }
    if (idx < HD) g_bias2[idx] = bl_ue[idx] + bl_se[idx];
    g_WeH[idx] = __float2half_rn(W_e[idx]);
    if (idx < HD * HD) {
        int n = idx >> 8, k = idx & 255;
        float w = Wr_ue[idx] + Wr_se[idx];
        __half wh = __float2half_rn(w);
        g_WcH[n * KB1 + k] = wh;
        g_WcL[n * KB1 + k] = __float2half_rn(w - __half2float(wh));
    }
}

// ---------------- prep2: rank-11 correction columns of W' -------------------
__global__ void prep2_kernel(const float* __restrict__ Wl_ue, const float* __restrict__ W_u,
                             const float* __restrict__ b_u,
                             const float* __restrict__ Wl_se, const float* __restrict__ W_s,
                             const float* __restrict__ b_s) {
    int n = blockIdx.x;
    int c = threadIdx.x;    // 0..31
    float acc = 0.f;
    if (c < 8) {
        for (int h = 0; h < HD; h++) acc += Wl_ue[n * HD + h] * W_u[h * 8 + c];
    } else if (c == 8) {
        for (int h = 0; h < HD; h++) acc += Wl_ue[n * HD + h] * b_u[h];
    } else if (c == 9) {
        for (int h = 0; h < HD; h++) acc += Wl_se[n * HD + h] * W_s[h];
    } else if (c == 10) {
        for (int h = 0; h < HD; h++) acc += Wl_se[n * HD + h] * b_s[h];
    }
    __half h = __float2half_rn(acc);
    g_WcH[n * KB1 + 256 + c] = h;
    g_WcL[n * KB1 + 256 + c] = __float2half_rn(acc - __half2float(h));
}

// ---------------- merged edge aggregation -----------------------------------
__global__ void agg_kernel(const int* __restrict__ ue_src, const int* __restrict__ ue_dst,
                           const float* __restrict__ x_url, int n_ue,
                           const int* __restrict__ se_src, const int* __restrict__ se_dst,
                           const float* __restrict__ x_sender, int n_se) {
    int e = blockIdx.x * blockDim.x + threadIdx.x;
    if (e < n_ue) {
        int s = ue_src[e], d = ue_dst[e];
        const float4* xu = (const float4*)(x_url + (size_t)s * 8);
        float4 a = xu[0], b = xu[1];
        float* p = g_sum8 + (size_t)d * 8;
        asm volatile("red.global.add.v4.f32 [%0], {%1,%2,%3,%4};"
                     :: "l"(p), "f"(a.x), "f"(a.y), "f"(a.z), "f"(a.w) : "memory");
        asm volatile("red.global.add.v4.f32 [%0], {%1,%2,%3,%4};"
                     :: "l"(p + 4), "f"(b.x), "f"(b.y), "f"(b.z), "f"(b.w) : "memory");
        asm volatile("red.global.add.s32 [%0], %1;" :: "l"(g_cnt_ue + d), "r"(1) : "memory");
    } else {
        int e2 = e - n_ue;
        if (e2 < n_se) {
            int d = se_dst[e2];
            float v = x_sender[se_src[e2]];
            asm volatile("red.global.add.f32 [%0], %1;" :: "l"(g_sum1 + d), "f"(v) : "memory");
            asm volatile("red.global.add.s32 [%0], %1;" :: "l"(g_cnt_se + d), "r"(1) : "memory");
        }
    }
}

// ---------------- cp.async helpers ------------------------------------------
__device__ __forceinline__ void cp16(uint32_t d, const void* s, int sz) {
    asm volatile("cp.async.cg.shared.global [%0], [%1], 16, %2;"
                 :: "r"(d), "l"(s), "r"(sz));
}
#define CP_COMMIT() asm volatile("cp.async.commit_group;")
#define CP_WAIT0()  asm volatile("cp.async.wait_group 0;")

__device__ __forceinline__ void ldsm4(uint32_t addr, uint32_t& r0, uint32_t& r1,
                                      uint32_t& r2, uint32_t& r3) {
    asm volatile("ldmatrix.sync.aligned.m8n8.x4.shared.b16 {%0,%1,%2,%3}, [%4];"
                 : "=r"(r0), "=r"(r1), "=r"(r2), "=r"(r3) : "r"(addr));
}

__device__ __forceinline__ void mma16816(float* c, const uint32_t* a, uint32_t b0, uint32_t b1) {
    asm volatile("mma.sync.aligned.m16n8k16.row.col.f32.f16.f16.f32 "
                 "{%0,%1,%2,%3}, {%4,%5,%6,%7}, {%8,%9}, {%0,%1,%2,%3};"
                 : "+f"(c[0]), "+f"(c[1]), "+f"(c[2]), "+f"(c[3])
                 : "r"(a[0]), "r"(a[1]), "r"(a[2]), "r"(a[3]), "r"(b0), "r"(b1));
}

// ---------------- fully fused: proj + conv + activation + KAN ---------------
// Phase 1: he_pre[128x256] = x_email_tile @ W_e^T + b_e -> fp16 A2 (SMEM)
//          + rank-11 q vector into A2 cols 256..287
// Phase 2: conv = A2[128x288] @ W'^T + bias2 (hi+lo weights)
//          epilogue: 0.5x, leaky, gated residual -> he fp32 in registers
// Phase 3: he -> SMEM fp32; per-row KAN (SiLU base + cubic B-spline) -> out
__global__ __launch_bounds__(512) void fused_gemm(const float* __restrict__ x_email,
                                                  const float* __restrict__ b_e,
                                                  const float* __restrict__ gate,
                                                  const float* __restrict__ base_w,
                                                  const float* __restrict__ spline_w,
                                                  float* __restrict__ out) {
    extern __shared__ __half dsm[];
    const uint32_t sbase = (uint32_t)__cvta_generic_to_shared(dsm);
    __half* A2 = dsm;
    float* kanw = (float*)(dsm + KAN_OFF);   // sbw[512] + ssw[4096] ([g][o][h])

    const int tid = threadIdx.x;
    const int lane = tid & 31;
    const int warp = tid >> 5;      // 0..15
    const int wm = warp & 1;        // 2 m-slabs of 64
    const int wn = warp >> 1;       // 8 n-slabs of 32
    const int m0 = blockIdx.x * 128;

    const int a_row_off = ((lane >> 3) & 1) * 8 + (lane & 7);
    const int a_k_off   = ((lane >> 4) & 1) * 8;
    const int b_row_off = ((lane >> 4) & 1) * 8 + (lane & 7);
    const int b_k_off   = ((lane >> 3) & 1) * 8;
    const int g = lane >> 2, t = lane & 3;

    // ---- KAN weight load (rearranged ssw for conflict-free access) ----
    kanw[tid] = base_w[tid];                      // 512 floats
    for (int i = tid; i < 4096; i += 512) {
        int o = i >> 11;
        int h = (i >> 3) & 255;
        int gg = i & 7;
        kanw[512 + gg * 512 + o * 256 + h] = spline_w[i];
    }

    float C[4][4][4];
#pragma unroll
    for (int i = 0; i < 4; i++)
#pragma unroll
        for (int j = 0; j < 4; j++)
#pragma unroll
            for (int q = 0; q < 4; q++) C[i][j][q] = 0.f;

    float4 Ar[2];

    // ================= PHASE 1: K = 768 =================
    auto issueB1 = [&](int kt, int buf) {
        const int k0 = kt * 32;
        uint32_t bh = sbase + (uint32_t)(S0 + buf * P1_STAGE + 5120) * 2u;
#pragma unroll
        for (int i = 0; i < 2; i++) {
            int f = tid + i * 512;          // 256 rows x 4 chunks
            int row = f >> 2, m = f & 3;
            cp16(bh + (uint32_t)(row * 40 + m * 8) * 2,
                 g_WeH + (size_t)row * KD + k0 + m * 8, 16);
        }
        CP_COMMIT();
    };
    auto loadA1 = [&](int kt) {
        const int k0 = kt * 32;
#pragma unroll
        for (int i = 0; i < 2; i++) {
            int f = tid + i * 512;          // 128 rows x 8 float4
            int row = f >> 3, c4 = (f & 7) << 2;
            int gr = m0 + row;
            Ar[i] = (gr < NE) ? *(const float4*)(x_email + (size_t)gr * KD + k0 + c4)
                              : make_float4(0.f, 0.f, 0.f, 0.f);
        }
    };
    auto storeA1 = [&](int buf) {
        __half* Ah = dsm + S0 + buf * P1_STAGE;
#pragma unroll
        for (int i = 0; i < 2; i++) {
            int f = tid + i * 512;
            int row = f >> 3, c4 = (f & 7) << 2;
            float4 v = Ar[i];
            __half2 hp0; hp0.x = __float2half_rn(v.x); hp0.y = __float2half_rn(v.y);
            __half2 hp1; hp1.x = __float2half_rn(v.z); hp1.y = __float2half_rn(v.w);
            *(__half2*)(Ah + row * 40 + c4)     = hp0;
            *(__half2*)(Ah + row * 40 + c4 + 2) = hp1;
        }
    };

    loadA1(0);
    issueB1(0, 0);

    for (int kt = 0; kt < 24; kt++) {
        const int cur = kt & 1;
        storeA1(cur);
        CP_WAIT0();
        __syncthreads();
        if (kt + 1 < 24) {
            issueB1(kt + 1, cur ^ 1);
            loadA1(kt + 1);
        }
        const uint32_t sAh = sbase + (uint32_t)(S0 + cur * P1_STAGE) * 2u;
        const uint32_t sBh = sbase + (uint32_t)(S0 + cur * P1_STAGE + 5120) * 2u;
#pragma unroll
        for (int kh = 0; kh < 2; kh++) {
            uint32_t Af[4][4];
#pragma unroll
            for (int mf = 0; mf < 4; mf++) {
                int row = wm * 64 + mf * 16 + a_row_off;
                uint32_t off = (uint32_t)(row * 40 + kh * 16 + a_k_off) * 2;
                ldsm4(sAh + off, Af[mf][0], Af[mf][1], Af[mf][2], Af[mf][3]);
            }
            uint32_t Bf[2][4];
#pragma unroll
            for (int nf = 0; nf < 2; nf++) {
                int row = wn * 32 + nf * 16 + b_row_off;
                uint32_t off = (uint32_t)(row * 40 + kh * 16 + b_k_off) * 2;
                ldsm4(sBh + off, Bf[nf][0], Bf[nf][1], Bf[nf][2], Bf[nf][3]);
            }
#pragma unroll
            for (int mf = 0; mf < 4; mf++) {
#pragma unroll
                for (int j = 0; j < 4; j++) {
                    int nf = j >> 1;
                    int hh = j & 1;
                    mma16816(C[mf][j], Af[mf], Bf[nf][hh * 2], Bf[nf][hh * 2 + 1]);
                }
            }
        }
    }

    // ---- epilogue 1: he_pre + b_e -> fp16 A2 cols 0..255
#pragma unroll
    for (int mf = 0; mf < 4; mf++) {
        int rl0 = wm * 64 + mf * 16 + g;
#pragma unroll
        for (int j = 0; j < 4; j++) {
            int col = wn * 32 + j * 8 + t * 2;
            float b0 = b_e[col], b1 = b_e[col + 1];
#pragma unroll
            for (int half = 0; half < 2; half++) {
                int rl = rl0 + half * 8;
                __half2 hp;
                hp.x = __float2half_rn(C[mf][j][half * 2 + 0] + b0);
                hp.y = __float2half_rn(C[mf][j][half * 2 + 1] + b1);
                *(__half2*)&A2[rl * A2_STRIDE + col] = hp;
            }
        }
    }

    // ---- q vector: A2 cols 256..287 (4 threads per row, 8 cols each)
    {
        int rl = tid >> 2;
        int cc = (tid & 3) * 8;
        int gr = m0 + rl;
        float qv[8];
#pragma unroll
        for (int i = 0; i < 8; i++) qv[i] = 0.f;
        if (gr < NE) {
            if (cc == 0) {
                int cu = g_cnt_ue[gr];
                if (cu > 0) {
                    float inv = 1.f / (float)cu;
#pragma unroll
                    for (int c = 0; c < 8; c++) qv[c] = g_sum8[(size_t)gr * 8 + c] * inv;
                }
            } else if (cc == 8) {
                if (g_cnt_ue[gr] > 0) qv[0] = 1.f;      // k=264 flag_u
                int cs = g_cnt_se[gr];
                if (cs > 0) {
                    qv[1] = g_sum1[gr] / (float)cs;     // k=265 mean_s
                    qv[2] = 1.f;                        // k=266 flag_s
                }
            }
        }
#pragma unroll
        for (int i = 0; i < 8; i += 2) {
            __half2 hp;
            hp.x = __float2half_rn(qv[i]);
            hp.y = __float2half_rn(qv[i + 1]);
            *(__half2*)&A2[rl * A2_STRIDE + 256 + cc + i] = hp;
        }
    }
    __syncthreads();

    // ================= PHASE 2: K = 288 =================
#pragma unroll
    for (int i = 0; i < 4; i++)
#pragma unroll
        for (int j = 0; j < 4; j++)
#pragma unroll
            for (int q = 0; q < 4; q++) C[i][j][q] = 0.f;

    auto issueB2 = [&](int kt, int buf) {
        const int k0 = kt * 32;
        uint32_t bh = sbase + (uint32_t)(S0 + buf * P2_STAGE) * 2u;
        uint32_t bl = bh + 10240u * 2u;
#pragma unroll
        for (int i = 0; i < 2; i++) {
            int f = tid + i * 512;
            int row = f >> 2, m = f & 3;
            uint32_t so = (uint32_t)(row * 40 + m * 8) * 2;
            size_t go = (size_t)row * KB1 + k0 + m * 8;
            cp16(bh + so, g_WcH + go, 16);
            cp16(bl + so, g_WcL + go, 16);
        }
        CP_COMMIT();
    };

    issueB2(0, 0);

    for (int kt = 0; kt < 9; kt++) {
        const int cur = kt & 1;
        CP_WAIT0();
        __syncthreads();
        if (kt + 1 < 9) issueB2(kt + 1, cur ^ 1);

        const uint32_t sBh = sbase + (uint32_t)(S0 + cur * P2_STAGE) * 2u;
        const uint32_t sBl = sBh + 10240u * 2u;
#pragma unroll
        for (int kh = 0; kh < 2; kh++) {
            uint32_t Af[4][4];
#pragma unroll
            for (int mf = 0; mf < 4; mf++) {
                int row = wm * 64 + mf * 16 + a_row_off;
                uint32_t off = (uint32_t)(row * A2_STRIDE + kt * 32 + kh * 16 + a_k_off) * 2;
                ldsm4(sbase + off, Af[mf][0], Af[mf][1], Af[mf][2], Af[mf][3]);
            }
            uint32_t Bfh[2][4], Bfl[2][4];
#pragma unroll
            for (int nf = 0; nf < 2; nf++) {
                int row = wn * 32 + nf * 16 + b_row_off;
                uint32_t off = (uint32_t)(row * 40 + kh * 16 + b_k_off) * 2;
                ldsm4(sBh + off, Bfh[nf][0], Bfh[nf][1], Bfh[nf][2], Bfh[nf][3]);
                ldsm4(sBl + off, Bfl[nf][0], Bfl[nf][1], Bfl[nf][2], Bfl[nf][3]);
            }
#pragma unroll
            for (int mf = 0; mf < 4; mf++) {
#pragma unroll
                for (int j = 0; j < 4; j++) {
                    int nf = j >> 1;
                    int hh = j & 1;
                    mma16816(C[mf][j], Af[mf], Bfh[nf][hh * 2], Bfh[nf][hh * 2 + 1]);
                    mma16816(C[mf][j], Af[mf], Bfl[nf][hh * 2], Bfl[nf][hh * 2 + 1]);
                }
            }
        }
    }

    // ---- epilogue 2: bias2, 0.5x, leaky, gated residual -> he in C regs
    const float alpha = 1.f / (1.f + expf(-gate[0]));
#pragma unroll
    for (int mf = 0; mf < 4; mf++) {
        int rl0 = wm * 64 + mf * 16 + g;
#pragma unroll
        for (int j = 0; j < 4; j++) {
            int col = wn * 32 + j * 8 + t * 2;
            float b0 = g_bias2[col], b1 = g_bias2[col + 1];
#pragma unroll
            for (int half = 0; half < 2; half++) {
                int rl = rl0 + half * 8;
                float v0 = C[mf][j][half * 2 + 0] + b0;
                float v1 = C[mf][j][half * 2 + 1] + b1;
                __half2 rh = *(const __half2*)&A2[rl * A2_STRIDE + col];
                float u;
                u = 0.5f * v0; u = u > 0.f ? u : 0.2f * u;
                C[mf][j][half * 2 + 0] = alpha * u + (1.f - alpha) * __half2float(rh.x);
                u = 0.5f * v1; u = u > 0.f ? u : 0.2f * u;
                C[mf][j][half * 2 + 1] = alpha * u + (1.f - alpha) * __half2float(rh.y);
            }
        }
    }
    __syncthreads();   // all A2 residual reads done before fp32 he overwrites region

    // ---- he fp32 -> SMEM (reuses A2+staging region; 128x256 floats)
    float* hem = (float*)dsm;
#pragma unroll
    for (int mf = 0; mf < 4; mf++) {
        int rl0 = wm * 64 + mf * 16 + g;
#pragma unroll
        for (int j = 0; j < 4; j++) {
            int col = wn * 32 + j * 8 + t * 2;
#pragma unroll
            for (int half = 0; half < 2; half++) {
                int rl = rl0 + half * 8;
                *(float2*)&hem[rl * 256 + col] =
                    make_float2(C[mf][j][half * 2 + 0], C[mf][j][half * 2 + 1]);
            }
        }
    }
    __syncthreads();

    // ================= PHASE 3: KAN =================
    const float* sbw = kanw;
    const float* ssw = kanw + 512;
    const float c6 = 1.f / 6.f;
#pragma unroll
    for (int rr = 0; rr < 8; rr++) {
        int rl = warp * 8 + rr;
        int row = m0 + rl;
        if (row >= NE) continue;
        float acc0 = 0.f, acc1 = 0.f;
#pragma unroll
        for (int it = 0; it < 8; it++) {
            int h = it * 32 + lane;
            float x = hem[rl * 256 + h];
            float sil = x * __fdividef(1.f, 1.f + __expf(-x));
            acc0 += sil * sbw[h];
            acc1 += sil * sbw[256 + h];
            float tt = (x + 2.2f) * 2.5f;
            float fj = floorf(tt);
            int j = (int)fj;
            if (j >= 0 && j < 11) {
                float u = tt - fj;
                float u2 = u * u, u3 = u2 * u;
                float p0 = u3 * c6;
                float p1 = (1.f + 3.f * (u + u2) - 3.f * u3) * c6;
                float p2 = (4.f - 6.f * u2 + 3.f * u3) * c6;
                float om = 1.f - u;
                float p3 = om * om * om * c6;
                if (j < 8) {
                    acc0 += p0 * ssw[j * 512 + h];
                    acc1 += p0 * ssw[j * 512 + 256 + h];
                }
                int g1 = j - 1;
                if (g1 >= 0 && g1 < 8) {
                    acc0 += p1 * ssw[g1 * 512 + h];
                    acc1 += p1 * ssw[g1 * 512 + 256 + h];
                }
                int g2 = j - 2;
                if (g2 >= 0 && g2 < 8) {
                    acc0 += p2 * ssw[g2 * 512 + h];
                    acc1 += p2 * ssw[g2 * 512 + 256 + h];
                }
                int g3 = j - 3;
                if (g3 >= 0) {
                    acc0 += p3 * ssw[g3 * 512 + h];
                    acc1 += p3 * ssw[g3 * 512 + 256 + h];
                }
            }
        }
#pragma unroll
        for (int off = 16; off; off >>= 1) {
            acc0 += __shfl_xor_sync(0xffffffff, acc0, off);
            acc1 += __shfl_xor_sync(0xffffffff, acc1, off);
        }
        if (lane == 0) {
            out[row * 2 + 0] = acc0;
            out[row * 2 + 1] = acc1;
        }
    }
}

// ---------------- launch ----------------------------------------------------
extern "C" void kernel_launch(void* const* d_in, const int* in_sizes, int n_in,
                              void* d_out, int out_size) {
    const float* x_email   = (const float*)d_in[0];
    const float* x_url     = (const float*)d_in[1];
    const float* x_sender  = (const float*)d_in[2];
    const float* W_e       = (const float*)d_in[3];
    const float* b_e       = (const float*)d_in[4];
    const float* W_u       = (const float*)d_in[5];
    const float* b_u       = (const float*)d_in[6];
    const float* W_s       = (const float*)d_in[7];
    const float* b_s       = (const float*)d_in[8];
    const float* Wl_ue     = (const float*)d_in[12];
    const float* bl_ue     = (const float*)d_in[13];
    const float* Wr_ue     = (const float*)d_in[14];
    const float* Wl_se     = (const float*)d_in[15];
    const float* bl_se     = (const float*)d_in[16];
    const float* Wr_se     = (const float*)d_in[17];
    const float* gate      = (const float*)d_in[21];
    const float* kan_base  = (const float*)d_in[22];
    const float* kan_spline= (const float*)d_in[23];
    const int*   ue_src    = (const int*)d_in[26];
    const int*   ue_dst    = (const int*)d_in[27];
    const int*   se_src    = (const int*)d_in[28];
    const int*   se_dst    = (const int*)d_in[29];
    int n_ue = in_sizes[26];
    int n_se = in_sizes[28];
    float* out = (float*)d_out;

    cudaFuncSetAttribute((void*)fused_gemm, cudaFuncAttributeMaxDynamicSharedMemorySize,
                         SMEM_BYTES);

    prep_kernel<<<KD, 256>>>(W_e, Wr_ue, Wr_se, bl_ue, bl_se);
    prep2_kernel<<<HD, 32>>>(Wl_ue, W_u, b_u, Wl_se, W_s, b_s);
    agg_kernel<<<(n_ue + n_se + 255) / 256, 256>>>(ue_src, ue_dst, x_url, n_ue,
                                                   se_src, se_dst, x_sender, n_se);
    fused_gemm<<<(NE + 127) / 128, 512, SMEM_BYTES>>>(x_email, b_e, gate,
                                                      kan_base, kan_spline, out);
}

// round 11
// speedup vs baseline: 5.9742x; 1.0566x over previous
#include <cuda_runtime.h>
#include <cuda_fp16.h>
#include <stdint.h>
#include <math.h>

#define NE 50000
#define HD 256
#define KD 768
#define KB1 288   // phase-2 K: 256 he + 32 q (11 real + pad)

// SMEM layout (halves)
#define A2_STRIDE 296                            // 592 B row stride: conflict-free ldsm
#define A2_HALVES (128 * A2_STRIDE)              // 37888
#define S0 A2_HALVES                             // staging region base (halves)
#define P1_STAGE 15360                           // phase-1 stage: Ah(5120) + Bh(10240)
#define P2_STAGE 10240                           // phase-2 stage: Bh only
#define KAN_OFF (S0 + 2 * P1_STAGE)              // 68608 halves = 137216 B
#define KAN_FLOATS 4608                          // sbw 512 + ssw 4096
#define SMEM_BYTES (KAN_OFF * 2 + KAN_FLOATS * 4)  // 155648

// ---------------- scratch ----------------------------------------------------
__device__ __half g_WeH[HD * KD];          // W_e fp16 [n][k] k<768
__device__ __half g_WcH[HD * KB1];         // W' fp16 [n][k] k<288
__device__ float g_bias2[HD];              // bl_ue + bl_se
__device__ float g_sum8[NE * 8];
__device__ float g_sum1[NE];
__device__ int   g_cnt_ue[NE];
__device__ int   g_cnt_se[NE];

// ---------------- weight prep (+ accumulator zeroing, fused) ----------------
__global__ void prep_kernel(const float* __restrict__ W_e,
                            const float* __restrict__ Wr_ue, const float* __restrict__ Wr_se,
                            const float* __restrict__ bl_ue, const float* __restrict__ bl_se) {
    int idx = blockIdx.x * 256 + threadIdx.x;   // 196608 threads
    for (int j = idx; j < NE * 8; j += 196608) g_sum8[j] = 0.f;
    if (idx < NE) { g_sum1[idx] = 0.f; g_cnt_ue[idx] = 0; g_cnt_se[idx] = 0; }
    if (idx < HD) g_bias2[idx] = bl_ue[idx] + bl_se[idx];
    g_WeH[idx] = __float2half_rn(W_e[idx]);
    if (idx < HD * HD) {
        int n = idx >> 8, k = idx & 255;
        g_WcH[n * KB1 + k] = __float2half_rn(Wr_ue[idx] + Wr_se[idx]);
    }
}

// ---------------- prep2: rank-11 correction columns of W' -------------------
__global__ void prep2_kernel(const float* __restrict__ Wl_ue, const float* __restrict__ W_u,
                             const float* __restrict__ b_u,
                             const float* __restrict__ Wl_se, const float* __restrict__ W_s,
                             const float* __restrict__ b_s) {
    int n = blockIdx.x;
    int c = threadIdx.x;    // 0..31
    float acc = 0.f;
    if (c < 8) {
        for (int h = 0; h < HD; h++) acc += Wl_ue[n * HD + h] * W_u[h * 8 + c];
    } else if (c == 8) {
        for (int h = 0; h < HD; h++) acc += Wl_ue[n * HD + h] * b_u[h];
    } else if (c == 9) {
        for (int h = 0; h < HD; h++) acc += Wl_se[n * HD + h] * W_s[h];
    } else if (c == 10) {
        for (int h = 0; h < HD; h++) acc += Wl_se[n * HD + h] * b_s[h];
    }
    g_WcH[n * KB1 + 256 + c] = __float2half_rn(acc);
}

// ---------------- merged edge aggregation -----------------------------------
__global__ void agg_kernel(const int* __restrict__ ue_src, const int* __restrict__ ue_dst,
                           const float* __restrict__ x_url, int n_ue,
                           const int* __restrict__ se_src, const int* __restrict__ se_dst,
                           const float* __restrict__ x_sender, int n_se) {
    int e = blockIdx.x * blockDim.x + threadIdx.x;
    if (e < n_ue) {
        int s = ue_src[e], d = ue_dst[e];
        const float4* xu = (const float4*)(x_url + (size_t)s * 8);
        float4 a = xu[0], b = xu[1];
        float* p = g_sum8 + (size_t)d * 8;
        asm volatile("red.global.add.v4.f32 [%0], {%1,%2,%3,%4};"
                     :: "l"(p), "f"(a.x), "f"(a.y), "f"(a.z), "f"(a.w) : "memory");
        asm volatile("red.global.add.v4.f32 [%0], {%1,%2,%3,%4};"
                     :: "l"(p + 4), "f"(b.x), "f"(b.y), "f"(b.z), "f"(b.w) : "memory");
        asm volatile("red.global.add.s32 [%0], %1;" :: "l"(g_cnt_ue + d), "r"(1) : "memory");
    } else {
        int e2 = e - n_ue;
        if (e2 < n_se) {
            int d = se_dst[e2];
            float v = x_sender[se_src[e2]];
            asm volatile("red.global.add.f32 [%0], %1;" :: "l"(g_sum1 + d), "f"(v) : "memory");
            asm volatile("red.global.add.s32 [%0], %1;" :: "l"(g_cnt_se + d), "r"(1) : "memory");
        }
    }
}

// ---------------- cp.async helpers ------------------------------------------
__device__ __forceinline__ void cp16(uint32_t d, const void* s, int sz) {
    asm volatile("cp.async.cg.shared.global [%0], [%1], 16, %2;"
                 :: "r"(d), "l"(s), "r"(sz));
}
#define CP_COMMIT() asm volatile("cp.async.commit_group;")
#define CP_WAIT0()  asm volatile("cp.async.wait_group 0;")

__device__ __forceinline__ void ldsm4(uint32_t addr, uint32_t& r0, uint32_t& r1,
                                      uint32_t& r2, uint32_t& r3) {
    asm volatile("ldmatrix.sync.aligned.m8n8.x4.shared.b16 {%0,%1,%2,%3}, [%4];"
                 : "=r"(r0), "=r"(r1), "=r"(r2), "=r"(r3) : "r"(addr));
}

__device__ __forceinline__ void mma16816(float* c, const uint32_t* a, uint32_t b0, uint32_t b1) {
    asm volatile("mma.sync.aligned.m16n8k16.row.col.f32.f16.f16.f32 "
                 "{%0,%1,%2,%3}, {%4,%5,%6,%7}, {%8,%9}, {%0,%1,%2,%3};"
                 : "+f"(c[0]), "+f"(c[1]), "+f"(c[2]), "+f"(c[3])
                 : "r"(a[0]), "r"(a[1]), "r"(a[2]), "r"(a[3]), "r"(b0), "r"(b1));
}

// ---------------- fully fused: proj + conv + activation + KAN ---------------
// 1024 threads, 32 warps (4m x 8n), warp tile 32x32, block tile 128x256.
// Phase 1: he_pre = x_email_tile @ W_e^T + b_e -> fp16 A2 (SMEM) + q vector
// Phase 2: conv = A2[128x288] @ W'^T + bias2 (fp16-hi weights only)
//          epilogue: 0.5x, leaky, gated residual -> he fp32 in registers
// Phase 3: he -> SMEM fp32; per-row KAN -> out
__global__ __launch_bounds__(1024, 1) void fused_gemm(const float* __restrict__ x_email,
                                                      const float* __restrict__ b_e,
                                                      const float* __restrict__ gate,
                                                      const float* __restrict__ base_w,
                                                      const float* __restrict__ spline_w,
                                                      float* __restrict__ out) {
    extern __shared__ __half dsm[];
    const uint32_t sbase = (uint32_t)__cvta_generic_to_shared(dsm);
    __half* A2 = dsm;
    float* kanw = (float*)(dsm + KAN_OFF);   // sbw[512] + ssw[4096] ([g][o][h])

    const int tid = threadIdx.x;
    const int lane = tid & 31;
    const int warp = tid >> 5;      // 0..31
    const int wm = warp & 3;        // 4 m-slabs of 32
    const int wn = warp >> 2;       // 8 n-slabs of 32
    const int m0 = blockIdx.x * 128;

    const int a_row_off = ((lane >> 3) & 1) * 8 + (lane & 7);
    const int a_k_off   = ((lane >> 4) & 1) * 8;
    const int b_row_off = ((lane >> 4) & 1) * 8 + (lane & 7);
    const int b_k_off   = ((lane >> 3) & 1) * 8;
    const int g = lane >> 2, t = lane & 3;

    // ---- KAN weight load ----
    for (int i = tid; i < 512; i += 1024) kanw[i] = base_w[i];
    for (int i = tid; i < 4096; i += 1024) {
        int o = i >> 11;
        int h = (i >> 3) & 255;
        int gg = i & 7;
        kanw[512 + gg * 512 + o * 256 + h] = spline_w[i];
    }

    float C[2][4][4];
#pragma unroll
    for (int i = 0; i < 2; i++)
#pragma unroll
        for (int j = 0; j < 4; j++)
#pragma unroll
            for (int q = 0; q < 4; q++) C[i][j][q] = 0.f;

    float4 Ar;

    // ================= PHASE 1: K = 768 =================
    auto issueB1 = [&](int kt, int buf) {
        const int k0 = kt * 32;
        uint32_t bh = sbase + (uint32_t)(S0 + buf * P1_STAGE + 5120) * 2u;
        int row = tid >> 2, m = tid & 3;   // 256 rows x 4 chunks, 1 per thread
        cp16(bh + (uint32_t)(row * 40 + m * 8) * 2,
             g_WeH + (size_t)row * KD + k0 + m * 8, 16);
        CP_COMMIT();
    };
    auto loadA1 = [&](int kt) {
        const int k0 = kt * 32;
        int row = tid >> 3, c4 = (tid & 7) << 2;  // 128 rows x 8 float4
        int gr = m0 + row;
        Ar = (gr < NE) ? *(const float4*)(x_email + (size_t)gr * KD + k0 + c4)
                       : make_float4(0.f, 0.f, 0.f, 0.f);
    };
    auto storeA1 = [&](int buf) {
        __half* Ah = dsm + S0 + buf * P1_STAGE;
        int row = tid >> 3, c4 = (tid & 7) << 2;
        __half2 hp0; hp0.x = __float2half_rn(Ar.x); hp0.y = __float2half_rn(Ar.y);
        __half2 hp1; hp1.x = __float2half_rn(Ar.z); hp1.y = __float2half_rn(Ar.w);
        *(__half2*)(Ah + row * 40 + c4)     = hp0;
        *(__half2*)(Ah + row * 40 + c4 + 2) = hp1;
    };

    loadA1(0);
    issueB1(0, 0);

    for (int kt = 0; kt < 24; kt++) {
        const int cur = kt & 1;
        storeA1(cur);
        CP_WAIT0();
        __syncthreads();
        if (kt + 1 < 24) {
            issueB1(kt + 1, cur ^ 1);
            loadA1(kt + 1);
        }
        const uint32_t sAh = sbase + (uint32_t)(S0 + cur * P1_STAGE) * 2u;
        const uint32_t sBh = sbase + (uint32_t)(S0 + cur * P1_STAGE + 5120) * 2u;
#pragma unroll
        for (int kh = 0; kh < 2; kh++) {
            uint32_t Af[2][4];
#pragma unroll
            for (int mf = 0; mf < 2; mf++) {
                int row = wm * 32 + mf * 16 + a_row_off;
                uint32_t off = (uint32_t)(row * 40 + kh * 16 + a_k_off) * 2;
                ldsm4(sAh + off, Af[mf][0], Af[mf][1], Af[mf][2], Af[mf][3]);
            }
            uint32_t Bf[2][4];
#pragma unroll
            for (int nf = 0; nf < 2; nf++) {
                int row = wn * 32 + nf * 16 + b_row_off;
                uint32_t off = (uint32_t)(row * 40 + kh * 16 + b_k_off) * 2;
                ldsm4(sBh + off, Bf[nf][0], Bf[nf][1], Bf[nf][2], Bf[nf][3]);
            }
#pragma unroll
            for (int mf = 0; mf < 2; mf++) {
#pragma unroll
                for (int j = 0; j < 4; j++) {
                    int nf = j >> 1;
                    int hh = j & 1;
                    mma16816(C[mf][j], Af[mf], Bf[nf][hh * 2], Bf[nf][hh * 2 + 1]);
                }
            }
        }
    }

    // ---- epilogue 1: he_pre + b_e -> fp16 A2 cols 0..255
#pragma unroll
    for (int mf = 0; mf < 2; mf++) {
        int rl0 = wm * 32 + mf * 16 + g;
#pragma unroll
        for (int j = 0; j < 4; j++) {
            int col = wn * 32 + j * 8 + t * 2;
            float b0 = b_e[col], b1 = b_e[col + 1];
#pragma unroll
            for (int half = 0; half < 2; half++) {
                int rl = rl0 + half * 8;
                __half2 hp;
                hp.x = __float2half_rn(C[mf][j][half * 2 + 0] + b0);
                hp.y = __float2half_rn(C[mf][j][half * 2 + 1] + b1);
                *(__half2*)&A2[rl * A2_STRIDE + col] = hp;
            }
        }
    }

    // ---- q vector: A2 cols 256..287 (8 threads per row, 4 cols each)
    {
        int rl = tid >> 3;
        int cc = (tid & 7) * 4;
        int gr = m0 + rl;
        float qv[4];
#pragma unroll
        for (int i = 0; i < 4; i++) qv[i] = 0.f;
        if (gr < NE && cc < 12) {
            int cu = g_cnt_ue[gr];
            int cs = g_cnt_se[gr];
            float invu = (cu > 0) ? 1.f / (float)cu : 0.f;
#pragma unroll
            for (int i = 0; i < 4; i++) {
                int qi = cc + i;
                float v = 0.f;
                if (qi < 8)       v = g_sum8[(size_t)gr * 8 + qi] * invu;
                else if (qi == 8)  v = (cu > 0) ? 1.f : 0.f;
                else if (qi == 9)  v = (cs > 0) ? g_sum1[gr] / (float)cs : 0.f;
                else if (qi == 10) v = (cs > 0) ? 1.f : 0.f;
                qv[i] = v;
            }
        }
        __half2 hp0; hp0.x = __float2half_rn(qv[0]); hp0.y = __float2half_rn(qv[1]);
        __half2 hp1; hp1.x = __float2half_rn(qv[2]); hp1.y = __float2half_rn(qv[3]);
        *(__half2*)&A2[rl * A2_STRIDE + 256 + cc]     = hp0;
        *(__half2*)&A2[rl * A2_STRIDE + 256 + cc + 2] = hp1;
    }
    __syncthreads();

    // ================= PHASE 2: K = 288, fp16-hi weights =================
#pragma unroll
    for (int i = 0; i < 2; i++)
#pragma unroll
        for (int j = 0; j < 4; j++)
#pragma unroll
            for (int q = 0; q < 4; q++) C[i][j][q] = 0.f;

    auto issueB2 = [&](int kt, int buf) {
        const int k0 = kt * 32;
        uint32_t bh = sbase + (uint32_t)(S0 + buf * P2_STAGE) * 2u;
        int row = tid >> 2, m = tid & 3;
        cp16(bh + (uint32_t)(row * 40 + m * 8) * 2,
             g_WcH + (size_t)row * KB1 + k0 + m * 8, 16);
        CP_COMMIT();
    };

    issueB2(0, 0);

    for (int kt = 0; kt < 9; kt++) {
        const int cur = kt & 1;
        CP_WAIT0();
        __syncthreads();
        if (kt + 1 < 9) issueB2(kt + 1, cur ^ 1);

        const uint32_t sBh = sbase + (uint32_t)(S0 + cur * P2_STAGE) * 2u;
#pragma unroll
        for (int kh = 0; kh < 2; kh++) {
            uint32_t Af[2][4];
#pragma unroll
            for (int mf = 0; mf < 2; mf++) {
                int row = wm * 32 + mf * 16 + a_row_off;
                uint32_t off = (uint32_t)(row * A2_STRIDE + kt * 32 + kh * 16 + a_k_off) * 2;
                ldsm4(sbase + off, Af[mf][0], Af[mf][1], Af[mf][2], Af[mf][3]);
            }
            uint32_t Bf[2][4];
#pragma unroll
            for (int nf = 0; nf < 2; nf++) {
                int row = wn * 32 + nf * 16 + b_row_off;
                uint32_t off = (uint32_t)(row * 40 + kh * 16 + b_k_off) * 2;
                ldsm4(sBh + off, Bf[nf][0], Bf[nf][1], Bf[nf][2], Bf[nf][3]);
            }
#pragma unroll
            for (int mf = 0; mf < 2; mf++) {
#pragma unroll
                for (int j = 0; j < 4; j++) {
                    int nf = j >> 1;
                    int hh = j & 1;
                    mma16816(C[mf][j], Af[mf], Bf[nf][hh * 2], Bf[nf][hh * 2 + 1]);
                }
            }
        }
    }

    // ---- epilogue 2: bias2, 0.5x, leaky, gated residual -> he in C regs
    const float alpha = 1.f / (1.f + expf(-gate[0]));
#pragma unroll
    for (int mf = 0; mf < 2; mf++) {
        int rl0 = wm * 32 + mf * 16 + g;
#pragma unroll
        for (int j = 0; j < 4; j++) {
            int col = wn * 32 + j * 8 + t * 2;
            float b0 = g_bias2[col], b1 = g_bias2[col + 1];
#pragma unroll
            for (int half = 0; half < 2; half++) {
                int rl = rl0 + half * 8;
                float v0 = C[mf][j][half * 2 + 0] + b0;
                float v1 = C[mf][j][half * 2 + 1] + b1;
                __half2 rh = *(const __half2*)&A2[rl * A2_STRIDE + col];
                float u;
                u = 0.5f * v0; u = u > 0.f ? u : 0.2f * u;
                C[mf][j][half * 2 + 0] = alpha * u + (1.f - alpha) * __half2float(rh.x);
                u = 0.5f * v1; u = u > 0.f ? u : 0.2f * u;
                C[mf][j][half * 2 + 1] = alpha * u + (1.f - alpha) * __half2float(rh.y);
            }
        }
    }
    __syncthreads();   // residual reads complete before fp32 he overwrites region

    // ---- he fp32 -> SMEM (aliases A2+staging; 128x256 floats)
    float* hem = (float*)dsm;
#pragma unroll
    for (int mf = 0; mf < 2; mf++) {
        int rl0 = wm * 32 + mf * 16 + g;
#pragma unroll
        for (int j = 0; j < 4; j++) {
            int col = wn * 32 + j * 8 + t * 2;
#pragma unroll
            for (int half = 0; half < 2; half++) {
                int rl = rl0 + half * 8;
                *(float2*)&hem[rl * 256 + col] =
                    make_float2(C[mf][j][half * 2 + 0], C[mf][j][half * 2 + 1]);
            }
        }
    }
    __syncthreads();

    // ================= PHASE 3: KAN =================
    const float* sbw = kanw;
    const float* ssw = kanw + 512;
    const float c6 = 1.f / 6.f;
#pragma unroll
    for (int rr = 0; rr < 4; rr++) {
        int rl = warp * 4 + rr;
        int row = m0 + rl;
        if (row >= NE) continue;
        float acc0 = 0.f, acc1 = 0.f;
#pragma unroll
        for (int it = 0; it < 8; it++) {
            int h = it * 32 + lane;
            float x = hem[rl * 256 + h];
            float sil = x * __fdividef(1.f, 1.f + __expf(-x));
            acc0 += sil * sbw[h];
            acc1 += sil * sbw[256 + h];
            float tt = (x + 2.2f) * 2.5f;
            float fj = floorf(tt);
            int j = (int)fj;
            if (j >= 0 && j < 11) {
                float u = tt - fj;
                float u2 = u * u, u3 = u2 * u;
                float p0 = u3 * c6;
                float p1 = (1.f + 3.f * (u + u2) - 3.f * u3) * c6;
                float p2 = (4.f - 6.f * u2 + 3.f * u3) * c6;
                float om = 1.f - u;
                float p3 = om * om * om * c6;
                if (j < 8) {
                    acc0 += p0 * ssw[j * 512 + h];
                    acc1 += p0 * ssw[j * 512 + 256 + h];
                }
                int g1 = j - 1;
                if (g1 >= 0 && g1 < 8) {
                    acc0 += p1 * ssw[g1 * 512 + h];
                    acc1 += p1 * ssw[g1 * 512 + 256 + h];
                }
                int g2 = j - 2;
                if (g2 >= 0 && g2 < 8) {
                    acc0 += p2 * ssw[g2 * 512 + h];
                    acc1 += p2 * ssw[g2 * 512 + 256 + h];
                }
                int g3 = j - 3;
                if (g3 >= 0) {
                    acc0 += p3 * ssw[g3 * 512 + h];
                    acc1 += p3 * ssw[g3 * 512 + 256 + h];
                }
            }
        }
#pragma unroll
        for (int off = 16; off; off >>= 1) {
            acc0 += __shfl_xor_sync(0xffffffff, acc0, off);
            acc1 += __shfl_xor_sync(0xffffffff, acc1, off);
        }
        if (lane == 0) {
            out[row * 2 + 0] = acc0;
            out[row * 2 + 1] = acc1;
        }
    }
}

// ---------------- launch ----------------------------------------------------
extern "C" void kernel_launch(void* const* d_in, const int* in_sizes, int n_in,
                              void* d_out, int out_size) {
    const float* x_email   = (const float*)d_in[0];
    const float* x_url     = (const float*)d_in[1];
    const float* x_sender  = (const float*)d_in[2];
    const float* W_e       = (const float*)d_in[3];
    const float* b_e       = (const float*)d_in[4];
    const float* W_u       = (const float*)d_in[5];
    const float* b_u       = (const float*)d_in[6];
    const float* W_s       = (const float*)d_in[7];
    const float* b_s       = (const float*)d_in[8];
    const float* Wl_ue     = (const float*)d_in[12];
    const float* bl_ue     = (const float*)d_in[13];
    const float* Wr_ue     = (const float*)d_in[14];
    const float* Wl_se     = (const float*)d_in[15];
    const float* bl_se     = (const float*)d_in[16];
    const float* Wr_se     = (const float*)d_in[17];
    const float* gate      = (const float*)d_in[21];
    const float* kan_base  = (const float*)d_in[22];
    const float* kan_spline= (const float*)d_in[23];
    const int*   ue_src    = (const int*)d_in[26];
    const int*   ue_dst    = (const int*)d_in[27];
    const int*   se_src    = (const int*)d_in[28];
    const int*   se_dst    = (const int*)d_in[29];
    int n_ue = in_sizes[26];
    int n_se = in_sizes[28];
    float* out = (float*)d_out;

    cudaFuncSetAttribute((void*)fused_gemm, cudaFuncAttributeMaxDynamicSharedMemorySize,
                         SMEM_BYTES);

    prep_kernel<<<KD, 256>>>(W_e, Wr_ue, Wr_se, bl_ue, bl_se);
    prep2_kernel<<<HD, 32>>>(Wl_ue, W_u, b_u, Wl_se, W_s, b_s);
    agg_kernel<<<(n_ue + n_se + 255) / 256, 256>>>(ue_src, ue_dst, x_url, n_ue,
                                                   se_src, se_dst, x_sender, n_se);
    fused_gemm<<<(NE + 127) / 128, 1024, SMEM_BYTES>>>(x_email, b_e, gate,
                                                       kan_base, kan_spline, out);
}